// round 1
// baseline (speedup 1.0000x reference)
#include <cuda_runtime.h>
#include <math.h>
#include <stdint.h>

// Problem constants
#define Bc   2
#define Tc   512
#define Cc   768
#define Hc   12
#define HDc  64
#define Vc   50304
#define Lc   12
#define Mc   (Bc * Tc)          // 1024 rows
#define EPSc 1e-5f
#define GELU_Kc 0.7978845608028654f

// ---------------- scratch (device globals; no allocations allowed) ----------
__device__ float g_x[Mc * Cc];
__device__ float g_h[Mc * Cc];
__device__ float g_qkv[Mc * 3 * Cc];
__device__ float g_y[Mc * Cc];
__device__ float g_fc[Mc * 4 * Cc];
__device__ float g_ww[Vc];
__device__ float g_xx[Mc];

// ---------------- reduction helpers ----------------------------------------
__device__ __forceinline__ float warpSum(float v) {
#pragma unroll
    for (int o = 16; o; o >>= 1) v += __shfl_xor_sync(0xffffffffu, v, o);
    return v;
}
__device__ __forceinline__ float warpMax(float v) {
#pragma unroll
    for (int o = 16; o; o >>= 1) v = fmaxf(v, __shfl_xor_sync(0xffffffffu, v, o));
    return v;
}
__device__ __forceinline__ float warpMin(float v) {
#pragma unroll
    for (int o = 16; o; o >>= 1) v = fminf(v, __shfl_xor_sync(0xffffffffu, v, o));
    return v;
}

// sm must have >= (nthreads/32) floats. Returns reduced value to all threads.
__device__ float blockSum(float v, float* sm) {
    int lane = threadIdx.x & 31, wid = threadIdx.x >> 5;
    int nw = blockDim.x >> 5;
    v = warpSum(v);
    if (lane == 0) sm[wid] = v;
    __syncthreads();
    float r = (threadIdx.x < nw) ? sm[threadIdx.x] : 0.0f;
    if (wid == 0) {
        r = warpSum(r);
        if (lane == 0) sm[0] = r;
    }
    __syncthreads();
    float out = sm[0];
    __syncthreads();
    return out;
}
__device__ float blockMax(float v, float* sm) {
    int lane = threadIdx.x & 31, wid = threadIdx.x >> 5;
    int nw = blockDim.x >> 5;
    v = warpMax(v);
    if (lane == 0) sm[wid] = v;
    __syncthreads();
    float r = (threadIdx.x < nw) ? sm[threadIdx.x] : -INFINITY;
    if (wid == 0) {
        r = warpMax(r);
        if (lane == 0) sm[0] = r;
    }
    __syncthreads();
    float out = sm[0];
    __syncthreads();
    return out;
}
__device__ float blockMin(float v, float* sm) {
    int lane = threadIdx.x & 31, wid = threadIdx.x >> 5;
    int nw = blockDim.x >> 5;
    v = warpMin(v);
    if (lane == 0) sm[wid] = v;
    __syncthreads();
    float r = (threadIdx.x < nw) ? sm[threadIdx.x] : INFINITY;
    if (wid == 0) {
        r = warpMin(r);
        if (lane == 0) sm[0] = r;
    }
    __syncthreads();
    float out = sm[0];
    __syncthreads();
    return out;
}

// ---------------- embedding -------------------------------------------------
__global__ void embed_kernel(const int* __restrict__ idx,
                             const float* __restrict__ wte,
                             const float* __restrict__ wpe,
                             float* __restrict__ x) {
    int m = blockIdx.x;
    int t = m % Tc;
    int row = idx[m];
    const float* wr = wte + (size_t)row * Cc;
    const float* pr = wpe + (size_t)t * Cc;
    float* xr = x + (size_t)m * Cc;
    for (int c = threadIdx.x; c < Cc; c += blockDim.x)
        xr[c] = wr[c] + pr[c];
}

// ---------------- layernorm (block per row) ---------------------------------
__global__ void ln_kernel(const float* __restrict__ in, float* __restrict__ out,
                          const float* __restrict__ w, const float* __restrict__ b) {
    __shared__ float sm[32];
    int m = blockIdx.x;
    const float* row = in + (size_t)m * Cc;
    float s = 0.f, ss = 0.f;
    for (int c = threadIdx.x; c < Cc; c += blockDim.x) {
        float v = row[c];
        s += v;
        ss += v * v;
    }
    float tot = blockSum(s, sm);
    float tot2 = blockSum(ss, sm);
    float mean = tot / Cc;
    float var = tot2 / Cc - mean * mean;
    float rstd = rsqrtf(var + EPSc);
    float* orow = out + (size_t)m * Cc;
    for (int c = threadIdx.x; c < Cc; c += blockDim.x)
        orow[c] = (row[c] - mean) * rstd * w[c] + b[c];
}

// ---------------- tiled SGEMM: out[M,N] = A[M,K] @ W[N,K]^T (+epilogue) -----
// MODE 0: + bias
// MODE 1: + bias + residual (res[m,n])
// MODE 2: + bias, then tanh-GELU
// MODE 3: plain (no bias) -- head GEMM
template <int MODE>
__global__ __launch_bounds__(256) void gemm_kernel(
    const float* __restrict__ A, const float* __restrict__ Wt,
    const float* __restrict__ bias, const float* __restrict__ res,
    float* __restrict__ out, int Mr, int Nr, int Kr) {
    const int BM = 64, BN = 64, BK = 16;
    __shared__ float As[BK][BM + 4];
    __shared__ float Bs[BK][BN + 4];
    int tid = threadIdx.x;
    int tm = tid >> 4;          // 0..15
    int tn = tid & 15;          // 0..15
    int bm = blockIdx.y * BM;
    int bn = blockIdx.x * BN;
    int lr = tid >> 2;          // 0..63 : row within tile for loading
    int lc = (tid & 3) * 4;     // 0,4,8,12 : k-offset for loading

    float acc[4][4];
#pragma unroll
    for (int i = 0; i < 4; i++)
#pragma unroll
        for (int j = 0; j < 4; j++) acc[i][j] = 0.f;

    const float* Arow = A + (size_t)(bm + lr) * Kr;
    const float* Brow = Wt + (size_t)(bn + lr) * Kr;

    for (int k0 = 0; k0 < Kr; k0 += BK) {
        float4 a = *(const float4*)(Arow + k0 + lc);
        float4 bb = *(const float4*)(Brow + k0 + lc);
        As[lc + 0][lr] = a.x; As[lc + 1][lr] = a.y;
        As[lc + 2][lr] = a.z; As[lc + 3][lr] = a.w;
        Bs[lc + 0][lr] = bb.x; Bs[lc + 1][lr] = bb.y;
        Bs[lc + 2][lr] = bb.z; Bs[lc + 3][lr] = bb.w;
        __syncthreads();
#pragma unroll
        for (int kk = 0; kk < BK; kk++) {
            float ra[4], rb[4];
#pragma unroll
            for (int i = 0; i < 4; i++) ra[i] = As[kk][tm * 4 + i];
#pragma unroll
            for (int j = 0; j < 4; j++) rb[j] = Bs[kk][tn * 4 + j];
#pragma unroll
            for (int i = 0; i < 4; i++)
#pragma unroll
                for (int j = 0; j < 4; j++) acc[i][j] += ra[i] * rb[j];
        }
        __syncthreads();
    }

#pragma unroll
    for (int i = 0; i < 4; i++) {
        int m = bm + tm * 4 + i;
#pragma unroll
        for (int j = 0; j < 4; j++) {
            int n = bn + tn * 4 + j;
            float v = acc[i][j];
            if (MODE != 3) v += bias[n];
            if (MODE == 1) v += res[(size_t)m * Nr + n];
            if (MODE == 2) {
                float t = v;
                v = 0.5f * t * (1.0f + tanhf(GELU_Kc * (t + 0.044715f * t * t * t)));
            }
            out[(size_t)m * Nr + n] = v;
        }
    }
}

// ---------------- fused causal attention (one block per (b,h,q)) ------------
__global__ __launch_bounds__(128) void attn_kernel(const float* __restrict__ qkv,
                                                   float* __restrict__ y) {
    int q = blockIdx.x, h = blockIdx.y, b = blockIdx.z;
    int tid = threadIdx.x;
    __shared__ float qv[HDc];
    __shared__ float s[Tc];
    __shared__ float sm[32];

    const float* base = qkv + (size_t)b * Tc * 3 * Cc;
    if (tid < HDc) qv[tid] = base[(size_t)q * 3 * Cc + h * HDc + tid];
    __syncthreads();

    const float scale = 0.125f;  // 1/sqrt(64)
    for (int k = tid; k <= q; k += 128) {
        const float* kv = base + (size_t)k * 3 * Cc + Cc + h * HDc;
        float d = 0.f;
#pragma unroll
        for (int i = 0; i < HDc; i++) d += qv[i] * kv[i];
        s[k] = d * scale;
    }
    __syncthreads();

    float mx = -INFINITY;
    for (int k = tid; k <= q; k += 128) mx = fmaxf(mx, s[k]);
    float MX = blockMax(mx, sm);

    float lsum = 0.f;
    for (int k = tid; k <= q; k += 128) {
        float e = expf(s[k] - MX);
        s[k] = e;
        lsum += e;
    }
    float SUM = blockSum(lsum, sm);
    __syncthreads();
    float inv = 1.0f / SUM;

    if (tid < HDc) {
        int d = tid;
        float acc = 0.f;
        const float* vbase = base + 2 * Cc + h * HDc + d;
        for (int k = 0; k <= q; k++) acc += s[k] * vbase[(size_t)k * 3 * Cc];
        y[((size_t)(b * Tc + q)) * Cc + h * HDc + d] = acc * inv;
    }
}

// ---------------- head helpers ----------------------------------------------
__global__ void ww_kernel(const float* __restrict__ wte, float* __restrict__ ww) {
    __shared__ float sm[32];
    int v = blockIdx.x;
    const float* row = wte + (size_t)v * Cc;
    float s = 0.f;
    for (int c = threadIdx.x; c < Cc; c += blockDim.x) {
        float t = row[c];
        s += t * t;
    }
    float tot = blockSum(s, sm);
    if (threadIdx.x == 0) ww[v] = tot;
}

__global__ void xx_kernel(const float* __restrict__ h, float* __restrict__ xx) {
    __shared__ float sm[32];
    int m = blockIdx.x;
    const float* row = h + (size_t)m * Cc;
    float s = 0.f;
    for (int c = threadIdx.x; c < Cc; c += blockDim.x) {
        float t = row[c];
        s += t * t;
    }
    float tot = blockSum(s, sm);
    if (threadIdx.x == 0) xx[m] = tot;
}

// Final head kernel: out currently holds wx[m,v]; rewrite in-place to logits.
__global__ __launch_bounds__(512) void dist_kernel(float* __restrict__ out,
                                                   const float* __restrict__ ww,
                                                   const float* __restrict__ xx) {
    __shared__ float sm[32];
    int m = blockIdx.x;
    float* row = out + (size_t)m * Vc;
    float xxm = xx[m];

    // phase 1: min of raw dist
    float mn = INFINITY;
    for (int v = threadIdx.x; v < Vc; v += blockDim.x) {
        float d = ww[v] + xxm - 2.0f * row[v];
        mn = fminf(mn, d);
    }
    float MN = blockMin(mn, sm);

    // phase 2: p = (d/min)^(-768), stage p into out, accumulate sum
    float lsum = 0.f;
    for (int v = threadIdx.x; v < Vc; v += blockDim.x) {
        float d = ww[v] + xxm - 2.0f * row[v];
        float r = d / MN;
        float p = expf(-768.0f * logf(r));   // r >= 1 (up to 1 ulp)
        if (!isfinite(p)) p = 0.0f;
        row[v] = p;
        lsum += p;
    }
    float TOT = blockSum(lsum, sm);
    float invTot = 1.0f / TOT;
    const float floorp = 0.01f / 50304.0f;

    // phase 3: logits
    for (int v = threadIdx.x; v < Vc; v += blockDim.x) {
        float p = row[v];
        row[v] = logf(p * invTot + floorp);
    }
}

// ---------------- launch -----------------------------------------------------
extern "C" void kernel_launch(void* const* d_in, const int* in_sizes, int n_in,
                              void* d_out, int out_size) {
    const int*   idx    = (const int*)d_in[0];
    const float* wte    = (const float*)d_in[1];
    const float* wpe    = (const float*)d_in[2];
    const float* ln1_w  = (const float*)d_in[3];
    const float* ln1_b  = (const float*)d_in[4];
    const float* attn_w = (const float*)d_in[5];
    const float* attn_b = (const float*)d_in[6];
    const float* proj_w = (const float*)d_in[7];
    const float* proj_b = (const float*)d_in[8];
    const float* ln2_w  = (const float*)d_in[9];
    const float* ln2_b  = (const float*)d_in[10];
    const float* fc_w   = (const float*)d_in[11];
    const float* fc_b   = (const float*)d_in[12];
    const float* fc2_w  = (const float*)d_in[13];
    const float* fc2_b  = (const float*)d_in[14];
    const float* lnf_w  = (const float*)d_in[15];
    const float* lnf_b  = (const float*)d_in[16];
    float* out = (float*)d_out;

    float *x, *h, *qkv, *y, *fc, *ww, *xx;
    cudaGetSymbolAddress((void**)&x, g_x);
    cudaGetSymbolAddress((void**)&h, g_h);
    cudaGetSymbolAddress((void**)&qkv, g_qkv);
    cudaGetSymbolAddress((void**)&y, g_y);
    cudaGetSymbolAddress((void**)&fc, g_fc);
    cudaGetSymbolAddress((void**)&ww, g_ww);
    cudaGetSymbolAddress((void**)&xx, g_xx);

    embed_kernel<<<Mc, 256>>>(idx, wte, wpe, x);
    ww_kernel<<<Vc, 128>>>(wte, ww);   // independent of layers

    for (int l = 0; l < Lc; l++) {
        const float* l1w = ln1_w + (size_t)l * Cc;
        const float* l1b = ln1_b + (size_t)l * Cc;
        const float* aw  = attn_w + (size_t)l * 3 * Cc * Cc;
        const float* ab  = attn_b + (size_t)l * 3 * Cc;
        const float* pw  = proj_w + (size_t)l * Cc * Cc;
        const float* pb  = proj_b + (size_t)l * Cc;
        const float* l2w = ln2_w + (size_t)l * Cc;
        const float* l2b = ln2_b + (size_t)l * Cc;
        const float* fw  = fc_w + (size_t)l * 4 * Cc * Cc;
        const float* fb  = fc_b + (size_t)l * 4 * Cc;
        const float* f2w = fc2_w + (size_t)l * Cc * 4 * Cc;
        const float* f2b = fc2_b + (size_t)l * Cc;

        // attention block
        ln_kernel<<<Mc, 256>>>(x, h, l1w, l1b);
        {
            dim3 g(3 * Cc / 64, Mc / 64);
            gemm_kernel<0><<<g, 256>>>(h, aw, ab, nullptr, qkv, Mc, 3 * Cc, Cc);
        }
        {
            dim3 g(Tc, Hc, Bc);
            attn_kernel<<<g, 128>>>(qkv, y);
        }
        {
            dim3 g(Cc / 64, Mc / 64);
            gemm_kernel<1><<<g, 256>>>(y, pw, pb, x, x, Mc, Cc, Cc);
        }

        // MLP block
        ln_kernel<<<Mc, 256>>>(x, h, l2w, l2b);
        {
            dim3 g(4 * Cc / 64, Mc / 64);
            gemm_kernel<2><<<g, 256>>>(h, fw, fb, nullptr, fc, Mc, 4 * Cc, Cc);
        }
        {
            dim3 g(Cc / 64, Mc / 64);
            gemm_kernel<1><<<g, 256>>>(fc, f2w, f2b, x, x, Mc, Cc, 4 * Cc);
        }
    }

    // final LN + head
    ln_kernel<<<Mc, 256>>>(x, h, lnf_w, lnf_b);
    xx_kernel<<<Mc, 256>>>(h, xx);
    {
        dim3 g(Vc / 64, Mc / 64);
        gemm_kernel<3><<<g, 256>>>(h, wte, nullptr, nullptr, out, Mc, Vc, Cc);
    }
    dist_kernel<<<Mc, 512>>>(out, ww, xx);
}

// round 2
// speedup vs baseline: 3.2032x; 3.2032x over previous
#include <cuda_runtime.h>
#include <math.h>
#include <stdint.h>

// Problem constants
#define Bc   2
#define Tc   512
#define Cc   768
#define Hc   12
#define HDc  64
#define Vc   50304
#define Lc   12
#define Mc   (Bc * Tc)          // 1024 rows
#define BHc  (Bc * Hc)          // 24
#define EPSc 1e-5f
#define GELU_Kc 0.7978845608028654f

// ---------------- scratch (device globals; no allocations allowed) ----------
__device__ float g_x[Mc * Cc];
__device__ float g_h[Mc * Cc];
__device__ float g_qkv[Mc * 3 * Cc];
__device__ float g_y[Mc * Cc];
__device__ float g_fc[Mc * 4 * Cc];
__device__ float g_s[BHc * Tc * Tc];          // attention scores / probs (25MB)
__device__ float g_vt[BHc * HDc * Tc];        // V transposed per (b,h): [d][k]
__device__ float g_ww[Vc];
__device__ float g_xx[Mc];

// ---------------- helpers ----------------------------------------------------
__device__ __forceinline__ float warpSum(float v) {
#pragma unroll
    for (int o = 16; o; o >>= 1) v += __shfl_xor_sync(0xffffffffu, v, o);
    return v;
}
__device__ __forceinline__ float warpMax(float v) {
#pragma unroll
    for (int o = 16; o; o >>= 1) v = fmaxf(v, __shfl_xor_sync(0xffffffffu, v, o));
    return v;
}
__device__ __forceinline__ float warpMin(float v) {
#pragma unroll
    for (int o = 16; o; o >>= 1) v = fminf(v, __shfl_xor_sync(0xffffffffu, v, o));
    return v;
}
__device__ float blockSum(float v, float* sm) {
    int lane = threadIdx.x & 31, wid = threadIdx.x >> 5;
    int nw = blockDim.x >> 5;
    v = warpSum(v);
    if (lane == 0) sm[wid] = v;
    __syncthreads();
    float r = (threadIdx.x < nw) ? sm[threadIdx.x] : 0.0f;
    if (wid == 0) { r = warpSum(r); if (lane == 0) sm[0] = r; }
    __syncthreads();
    float out = sm[0];
    __syncthreads();
    return out;
}
__device__ float blockMax(float v, float* sm) {
    int lane = threadIdx.x & 31, wid = threadIdx.x >> 5;
    int nw = blockDim.x >> 5;
    v = warpMax(v);
    if (lane == 0) sm[wid] = v;
    __syncthreads();
    float r = (threadIdx.x < nw) ? sm[threadIdx.x] : -INFINITY;
    if (wid == 0) { r = warpMax(r); if (lane == 0) sm[0] = r; }
    __syncthreads();
    float out = sm[0];
    __syncthreads();
    return out;
}
__device__ float blockMin(float v, float* sm) {
    int lane = threadIdx.x & 31, wid = threadIdx.x >> 5;
    int nw = blockDim.x >> 5;
    v = warpMin(v);
    if (lane == 0) sm[wid] = v;
    __syncthreads();
    float r = (threadIdx.x < nw) ? sm[threadIdx.x] : INFINITY;
    if (wid == 0) { r = warpMin(r); if (lane == 0) sm[0] = r; }
    __syncthreads();
    float out = sm[0];
    __syncthreads();
    return out;
}

__device__ __forceinline__ unsigned f2tf(float x) {
    unsigned r;
    asm("cvt.rna.tf32.f32 %0, %1;" : "=r"(r) : "f"(x));
    return r;
}

// ---------------- embedding --------------------------------------------------
__global__ void embed_kernel(const int* __restrict__ idx,
                             const float* __restrict__ wte,
                             const float* __restrict__ wpe,
                             float* __restrict__ x) {
    int m = blockIdx.x;
    int t = m % Tc;
    int row = idx[m];
    const float* wr = wte + (size_t)row * Cc;
    const float* pr = wpe + (size_t)t * Cc;
    float* xr = x + (size_t)m * Cc;
    for (int c = threadIdx.x; c < Cc; c += blockDim.x)
        xr[c] = wr[c] + pr[c];
}

// ---------------- layernorm --------------------------------------------------
__global__ void ln_kernel(const float* __restrict__ in, float* __restrict__ out,
                          const float* __restrict__ w, const float* __restrict__ b) {
    __shared__ float sm[32];
    int m = blockIdx.x;
    const float* row = in + (size_t)m * Cc;
    float s = 0.f, ss = 0.f;
    for (int c = threadIdx.x; c < Cc; c += blockDim.x) {
        float v = row[c];
        s += v; ss += v * v;
    }
    float tot = blockSum(s, sm);
    float tot2 = blockSum(ss, sm);
    float mean = tot / Cc;
    float var = tot2 / Cc - mean * mean;
    float rstd = rsqrtf(var + EPSc);
    float* orow = out + (size_t)m * Cc;
    for (int c = threadIdx.x; c < Cc; c += blockDim.x)
        orow[c] = (row[c] - mean) * rstd * w[c] + b[c];
}

// ---------------- generic tf32 MMA GEMM (NT): out = A @ B^T ------------------
// A: [M,K]-ish with row stride ldA;  B: [N,K]-ish with row stride ldB.
// Batched via blockIdx.z: z1 = z/nz2, z2 = z%nz2; base += z1*Z1 + z2*Z2.
// MODE 0: +bias  | 1: +bias+residual | 2: +bias+GELU | 3: plain
// CAUSAL: skip tiles fully above the diagonal (bn >= bm+128).
template <int MODE, bool CAUSAL>
__global__ __launch_bounds__(256) void mma_gemm(
    const float* __restrict__ A, long ldA, long aZ1, long aZ2,
    const float* __restrict__ B, long ldB, long bZ1, long bZ2,
    const float* __restrict__ bias,
    const float* __restrict__ res,
    float* __restrict__ Out, long ldO, long oZ1, long oZ2,
    int K, int nz2) {
    const int BM = 128, BN = 64, BK = 16;
    int bm = blockIdx.y * BM;
    int bn = blockIdx.x * BN;
    if (CAUSAL && bn >= bm + BM) return;

    int z = blockIdx.z;
    int z1 = z / nz2, z2 = z - z1 * nz2;
    A   += (size_t)z1 * aZ1 + (size_t)z2 * aZ2;
    B   += (size_t)z1 * bZ1 + (size_t)z2 * bZ2;
    Out += (size_t)z1 * oZ1 + (size_t)z2 * oZ2;
    const float* Res = res ? res + (size_t)z1 * oZ1 + (size_t)z2 * oZ2 : nullptr;

    __shared__ unsigned As[BM][BK + 4];   // [m][k], pad 4 -> stride 20
    __shared__ unsigned Bs[BN][BK + 4];

    int tid = threadIdx.x;
    int lane = tid & 31;
    int wid = tid >> 5;
    int g = lane >> 2;       // 0..7
    int tq = lane & 3;       // 0..3
    int wm = (wid & 3) * 32; // warp m offset (4 warps in m)
    int wn = (wid >> 2) * 32;// warp n offset (2 warps in n)

    int lr = tid >> 2;       // 0..63
    int lk = (tid & 3) * 4;  // 0,4,8,12

    const float* aP0 = A + (size_t)(bm + lr) * ldA + lk;
    const float* aP1 = A + (size_t)(bm + lr + 64) * ldA + lk;
    const float* bP  = B + (size_t)(bn + lr) * ldB + lk;

    float c[2][4][4];
#pragma unroll
    for (int i = 0; i < 2; i++)
#pragma unroll
        for (int j = 0; j < 4; j++)
#pragma unroll
            for (int r = 0; r < 4; r++) c[i][j][r] = 0.f;

    for (int k0 = 0; k0 < K; k0 += BK) {
        float4 a0 = *(const float4*)(aP0 + k0);
        float4 a1 = *(const float4*)(aP1 + k0);
        float4 bb = *(const float4*)(bP + k0);
        *(uint4*)&As[lr][lk]      = make_uint4(f2tf(a0.x), f2tf(a0.y), f2tf(a0.z), f2tf(a0.w));
        *(uint4*)&As[lr + 64][lk] = make_uint4(f2tf(a1.x), f2tf(a1.y), f2tf(a1.z), f2tf(a1.w));
        *(uint4*)&Bs[lr][lk]      = make_uint4(f2tf(bb.x), f2tf(bb.y), f2tf(bb.z), f2tf(bb.w));
        __syncthreads();

#pragma unroll
        for (int ks = 0; ks < 2; ks++) {
            int kb = ks * 8;
            unsigned af[2][4], bf[4][2];
#pragma unroll
            for (int mi = 0; mi < 2; mi++) {
                int r0 = wm + mi * 16 + g;
                af[mi][0] = As[r0][kb + tq];
                af[mi][1] = As[r0 + 8][kb + tq];
                af[mi][2] = As[r0][kb + tq + 4];
                af[mi][3] = As[r0 + 8][kb + tq + 4];
            }
#pragma unroll
            for (int ni = 0; ni < 4; ni++) {
                int nn = wn + ni * 8 + g;
                bf[ni][0] = Bs[nn][kb + tq];
                bf[ni][1] = Bs[nn][kb + tq + 4];
            }
#pragma unroll
            for (int mi = 0; mi < 2; mi++)
#pragma unroll
                for (int ni = 0; ni < 4; ni++) {
                    asm volatile(
                        "mma.sync.aligned.m16n8k8.row.col.f32.tf32.tf32.f32 "
                        "{%0,%1,%2,%3},{%4,%5,%6,%7},{%8,%9},{%0,%1,%2,%3};\n"
                        : "+f"(c[mi][ni][0]), "+f"(c[mi][ni][1]),
                          "+f"(c[mi][ni][2]), "+f"(c[mi][ni][3])
                        : "r"(af[mi][0]), "r"(af[mi][1]), "r"(af[mi][2]), "r"(af[mi][3]),
                          "r"(bf[ni][0]), "r"(bf[ni][1]));
                }
        }
        __syncthreads();
    }

    // epilogue
#pragma unroll
    for (int mi = 0; mi < 2; mi++) {
        int m0 = bm + wm + mi * 16 + g;
#pragma unroll
        for (int ni = 0; ni < 4; ni++) {
            int n0 = bn + wn + ni * 8 + tq * 2;
#pragma unroll
            for (int r = 0; r < 4; r++) {
                int m = m0 + (r >> 1) * 8;
                int n = n0 + (r & 1);
                float v = c[mi][ni][r];
                if (MODE != 3) v += bias[n];
                if (MODE == 1) v += Res[(size_t)m * ldO + n];
                if (MODE == 2) {
                    float t = v;
                    v = 0.5f * t * (1.0f + tanhf(GELU_Kc * (t + 0.044715f * t * t * t)));
                }
                Out[(size_t)m * ldO + n] = v;
            }
        }
    }
}

// ---------------- causal softmax over scores --------------------------------
// S[z][q][k]: scale by 1/8, mask k>q, softmax, write probs (0 for k>q).
__global__ __launch_bounds__(256) void softmax_kernel(float* __restrict__ S) {
    __shared__ float sm[32];
    int q = blockIdx.x;
    int z = blockIdx.y;
    float* row = S + ((size_t)z * Tc + q) * Tc;
    const float scale = 0.125f;

    float mx = -INFINITY;
    for (int k = threadIdx.x; k <= q; k += blockDim.x)
        mx = fmaxf(mx, row[k] * scale);
    float MX = blockMax(mx, sm);

    float lsum = 0.f;
    for (int k = threadIdx.x; k <= q; k += blockDim.x) {
        float e = expf(row[k] * scale - MX);
        row[k] = e;
        lsum += e;
    }
    float SUM = blockSum(lsum, sm);
    float inv = 1.0f / SUM;
    for (int k = threadIdx.x; k < Tc; k += blockDim.x)
        row[k] = (k <= q) ? row[k] * inv : 0.0f;
}

// ---------------- V transpose: vt[z][d][k] = qkv[b,k, 2C + h*64 + d] ---------
__global__ __launch_bounds__(256) void vtrans_kernel(const float* __restrict__ qkv,
                                                     float* __restrict__ vt) {
    __shared__ float sh[32][65];
    int kt = blockIdx.x;          // k-tile of 32
    int z = blockIdx.y;           // b*H + h
    int b = z / Hc, h = z - b * Hc;
    const float* base = qkv + (size_t)b * Tc * 3 * Cc + 2 * Cc + h * HDc;
    int k0 = kt * 32;
#pragma unroll
    for (int i = 0; i < 8; i++) {
        int idx = threadIdx.x + i * 256;
        int kl = idx >> 6, d = idx & 63;
        sh[kl][d] = base[(size_t)(k0 + kl) * 3 * Cc + d];
    }
    __syncthreads();
    float* vz = vt + (size_t)z * HDc * Tc;
#pragma unroll
    for (int i = 0; i < 8; i++) {
        int idx = threadIdx.x + i * 256;
        int kl = idx & 31, d = idx >> 5;
        vz[(size_t)d * Tc + k0 + kl] = sh[kl][d];
    }
}

// ---------------- head helpers -----------------------------------------------
__global__ void ww_kernel(const float* __restrict__ wte, float* __restrict__ ww) {
    __shared__ float sm[32];
    int v = blockIdx.x;
    const float* row = wte + (size_t)v * Cc;
    float s = 0.f;
    for (int c = threadIdx.x; c < Cc; c += blockDim.x) { float t = row[c]; s += t * t; }
    float tot = blockSum(s, sm);
    if (threadIdx.x == 0) ww[v] = tot;
}
__global__ void xx_kernel(const float* __restrict__ h, float* __restrict__ xx) {
    __shared__ float sm[32];
    int m = blockIdx.x;
    const float* row = h + (size_t)m * Cc;
    float s = 0.f;
    for (int c = threadIdx.x; c < Cc; c += blockDim.x) { float t = row[c]; s += t * t; }
    float tot = blockSum(s, sm);
    if (threadIdx.x == 0) xx[m] = tot;
}

__global__ __launch_bounds__(512) void dist_kernel(float* __restrict__ out,
                                                   const float* __restrict__ ww,
                                                   const float* __restrict__ xx) {
    __shared__ float sm[32];
    int m = blockIdx.x;
    float* row = out + (size_t)m * Vc;
    float xxm = xx[m];

    float mn = INFINITY;
    for (int v = threadIdx.x; v < Vc; v += blockDim.x) {
        float d = ww[v] + xxm - 2.0f * row[v];
        mn = fminf(mn, d);
    }
    float MN = blockMin(mn, sm);

    float lsum = 0.f;
    for (int v = threadIdx.x; v < Vc; v += blockDim.x) {
        float d = ww[v] + xxm - 2.0f * row[v];
        float r = d / MN;
        float p = expf(-768.0f * logf(r));
        if (!isfinite(p)) p = 0.0f;
        row[v] = p;
        lsum += p;
    }
    float TOT = blockSum(lsum, sm);
    float invTot = 1.0f / TOT;
    const float floorp = 0.01f / 50304.0f;

    for (int v = threadIdx.x; v < Vc; v += blockDim.x)
        row[v] = logf(row[v] * invTot + floorp);
}

// ---------------- launch ------------------------------------------------------
extern "C" void kernel_launch(void* const* d_in, const int* in_sizes, int n_in,
                              void* d_out, int out_size) {
    const int*   idx    = (const int*)d_in[0];
    const float* wte    = (const float*)d_in[1];
    const float* wpe    = (const float*)d_in[2];
    const float* ln1_w  = (const float*)d_in[3];
    const float* ln1_b  = (const float*)d_in[4];
    const float* attn_w = (const float*)d_in[5];
    const float* attn_b = (const float*)d_in[6];
    const float* proj_w = (const float*)d_in[7];
    const float* proj_b = (const float*)d_in[8];
    const float* ln2_w  = (const float*)d_in[9];
    const float* ln2_b  = (const float*)d_in[10];
    const float* fc_w   = (const float*)d_in[11];
    const float* fc_b   = (const float*)d_in[12];
    const float* fc2_w  = (const float*)d_in[13];
    const float* fc2_b  = (const float*)d_in[14];
    const float* lnf_w  = (const float*)d_in[15];
    const float* lnf_b  = (const float*)d_in[16];
    float* out = (float*)d_out;

    float *x, *h, *qkv, *y, *fc, *s, *vt, *ww, *xx;
    cudaGetSymbolAddress((void**)&x, g_x);
    cudaGetSymbolAddress((void**)&h, g_h);
    cudaGetSymbolAddress((void**)&qkv, g_qkv);
    cudaGetSymbolAddress((void**)&y, g_y);
    cudaGetSymbolAddress((void**)&fc, g_fc);
    cudaGetSymbolAddress((void**)&s, g_s);
    cudaGetSymbolAddress((void**)&vt, g_vt);
    cudaGetSymbolAddress((void**)&ww, g_ww);
    cudaGetSymbolAddress((void**)&xx, g_xx);

    embed_kernel<<<Mc, 256>>>(idx, wte, wpe, x);
    ww_kernel<<<Vc, 128>>>(wte, ww);

    const long S3C = 3 * Cc;
    for (int l = 0; l < Lc; l++) {
        const float* l1w = ln1_w + (size_t)l * Cc;
        const float* l1b = ln1_b + (size_t)l * Cc;
        const float* aw  = attn_w + (size_t)l * 3 * Cc * Cc;
        const float* ab  = attn_b + (size_t)l * 3 * Cc;
        const float* pw  = proj_w + (size_t)l * Cc * Cc;
        const float* pb  = proj_b + (size_t)l * Cc;
        const float* l2w = ln2_w + (size_t)l * Cc;
        const float* l2b = ln2_b + (size_t)l * Cc;
        const float* fw  = fc_w + (size_t)l * 4 * Cc * Cc;
        const float* fb  = fc_b + (size_t)l * 4 * Cc;
        const float* f2w = fc2_w + (size_t)l * Cc * 4 * Cc;
        const float* f2b = fc2_b + (size_t)l * Cc;

        ln_kernel<<<Mc, 256>>>(x, h, l1w, l1b);

        // qkv = h @ attn_w^T + attn_b   [1024, 2304]
        mma_gemm<0, false><<<dim3(3 * Cc / 64, Mc / 128, 1), 256>>>(
            h, Cc, 0, 0, aw, Cc, 0, 0, ab, nullptr, qkv, S3C, 0, 0, Cc, 1);

        // S[z,q,k] = Q @ K^T  (batched over z = b*H + h, causal tiles skipped)
        mma_gemm<3, true><<<dim3(Tc / 64, Tc / 128, BHc), 256>>>(
            qkv, S3C, (long)Tc * S3C, HDc,
            qkv + Cc, S3C, (long)Tc * S3C, HDc,
            nullptr, nullptr,
            s, Tc, (long)Hc * Tc * Tc, (long)Tc * Tc, HDc, Hc);

        softmax_kernel<<<dim3(Tc, BHc), 256>>>(s);
        vtrans_kernel<<<dim3(Tc / 32, BHc), 256>>>(qkv, vt);

        // y[b,q, h*64+d] = P @ V^T  (batched)
        mma_gemm<3, false><<<dim3(HDc / 64, Tc / 128, BHc), 256>>>(
            s, Tc, (long)Hc * Tc * Tc, (long)Tc * Tc,
            vt, Tc, (long)Hc * HDc * Tc, (long)HDc * Tc,
            nullptr, nullptr,
            y, Cc, (long)Tc * Cc, HDc, Tc, Hc);

        // x = x + y @ proj_w^T + proj_b
        mma_gemm<1, false><<<dim3(Cc / 64, Mc / 128, 1), 256>>>(
            y, Cc, 0, 0, pw, Cc, 0, 0, pb, x, x, Cc, 0, 0, Cc, 1);

        ln_kernel<<<Mc, 256>>>(x, h, l2w, l2b);

        // fc = gelu(h @ fc_w^T + fc_b)  [1024, 3072]
        mma_gemm<2, false><<<dim3(4 * Cc / 64, Mc / 128, 1), 256>>>(
            h, Cc, 0, 0, fw, Cc, 0, 0, fb, nullptr, fc, 4 * Cc, 0, 0, Cc, 1);

        // x = x + fc @ fc2_w^T + fc2_b
        mma_gemm<1, false><<<dim3(Cc / 64, Mc / 128, 1), 256>>>(
            fc, 4 * Cc, 0, 0, f2w, 4 * Cc, 0, 0, f2b, x, x, Cc, 0, 0, 4 * Cc, 1);
    }

    ln_kernel<<<Mc, 256>>>(x, h, lnf_w, lnf_b);
    xx_kernel<<<Mc, 256>>>(h, xx);

    // wx = h @ wte^T  [1024, 50304]
    mma_gemm<3, false><<<dim3(Vc / 64, Mc / 128, 1), 256>>>(
        h, Cc, 0, 0, wte, Cc, 0, 0, nullptr, nullptr, out, Vc, 0, 0, Cc, 1);

    dist_kernel<<<Mc, 512>>>(out, ww, xx);
}

// round 5
// speedup vs baseline: 5.7435x; 1.7931x over previous
#include <cuda_runtime.h>
#include <cuda_fp16.h>
#include <math.h>
#include <stdint.h>

// Problem constants
#define Bc   2
#define Tc   512
#define Cc   768
#define Hc   12
#define HDc  64
#define Vc   50304
#define Lc   12
#define Mc   (Bc * Tc)          // 1024 rows
#define BHc  (Bc * Hc)          // 24
#define EPSc 1e-5f
#define GELU_Kc 0.7978845608028654f

// ---------------- scratch (device globals; no allocations allowed) ----------
__device__ float  g_x[Mc * Cc];
__device__ float  g_hf[Mc * Cc];
__device__ float  g_ww[Vc];
__device__ float  g_xx[Mc];

__device__ __half w_attn16[Lc * 3 * Cc * Cc];
__device__ __half w_proj16[Lc * Cc * Cc];
__device__ __half w_fc16[Lc * 4 * Cc * Cc];
__device__ __half w_fc216[Lc * Cc * 4 * Cc];
__device__ __half w_wte16[(size_t)Vc * Cc];

__device__ __half g_h16[Mc * Cc];
__device__ __half g_qkv16[Mc * 3 * Cc];
__device__ __half g_y16[Mc * Cc];
__device__ __half g_fc16[Mc * 4 * Cc];
__device__ __half g_s16[(size_t)BHc * Tc * Tc];
__device__ __half g_vt16[BHc * HDc * Tc];

// ---------------- reduction helpers -----------------------------------------
__device__ __forceinline__ float warpSum(float v) {
#pragma unroll
    for (int o = 16; o; o >>= 1) v += __shfl_xor_sync(0xffffffffu, v, o);
    return v;
}
__device__ __forceinline__ float warpMax(float v) {
#pragma unroll
    for (int o = 16; o; o >>= 1) v = fmaxf(v, __shfl_xor_sync(0xffffffffu, v, o));
    return v;
}
__device__ __forceinline__ float warpMin(float v) {
#pragma unroll
    for (int o = 16; o; o >>= 1) v = fminf(v, __shfl_xor_sync(0xffffffffu, v, o));
    return v;
}
__device__ float blockSum(float v, float* sm) {
    int lane = threadIdx.x & 31, wid = threadIdx.x >> 5;
    int nw = blockDim.x >> 5;
    v = warpSum(v);
    if (lane == 0) sm[wid] = v;
    __syncthreads();
    float r = (threadIdx.x < nw) ? sm[threadIdx.x] : 0.0f;
    if (wid == 0) { r = warpSum(r); if (lane == 0) sm[0] = r; }
    __syncthreads();
    float out = sm[0];
    __syncthreads();
    return out;
}
__device__ float blockMax(float v, float* sm) {
    int lane = threadIdx.x & 31, wid = threadIdx.x >> 5;
    int nw = blockDim.x >> 5;
    v = warpMax(v);
    if (lane == 0) sm[wid] = v;
    __syncthreads();
    float r = (threadIdx.x < nw) ? sm[threadIdx.x] : -INFINITY;
    if (wid == 0) { r = warpMax(r); if (lane == 0) sm[0] = r; }
    __syncthreads();
    float out = sm[0];
    __syncthreads();
    return out;
}
__device__ float blockMin(float v, float* sm) {
    int lane = threadIdx.x & 31, wid = threadIdx.x >> 5;
    int nw = blockDim.x >> 5;
    v = warpMin(v);
    if (lane == 0) sm[wid] = v;
    __syncthreads();
    float r = (threadIdx.x < nw) ? sm[threadIdx.x] : INFINITY;
    if (wid == 0) { r = warpMin(r); if (lane == 0) sm[0] = r; }
    __syncthreads();
    float out = sm[0];
    __syncthreads();
    return out;
}

// ---------------- low-level asm helpers --------------------------------------
__device__ __forceinline__ void cpasync16(void* smem, const void* g, int sz) {
    unsigned a = (unsigned)__cvta_generic_to_shared(smem);
    asm volatile("cp.async.cg.shared.global [%0], [%1], 16, %2;\n"
                 :: "r"(a), "l"(g), "r"(sz));
}
#define CP_COMMIT() asm volatile("cp.async.commit_group;\n")
#define CP_WAIT0()  asm volatile("cp.async.wait_group 0;\n")

__device__ __forceinline__ void ldsm4(unsigned& r0, unsigned& r1, unsigned& r2,
                                      unsigned& r3, const __half* p) {
    unsigned a = (unsigned)__cvta_generic_to_shared(p);
    asm volatile("ldmatrix.sync.aligned.m8n8.x4.shared.b16 {%0,%1,%2,%3}, [%4];\n"
                 : "=r"(r0), "=r"(r1), "=r"(r2), "=r"(r3) : "r"(a));
}

__device__ __forceinline__ float geluf(float t) {
    return 0.5f * t * (1.0f + tanhf(GELU_Kc * (t + 0.044715f * t * t * t)));
}

// ---------------- f32 -> f16 convert ------------------------------------------
__global__ void f2h_kernel(const float* __restrict__ src, __half* __restrict__ dst,
                           long n2) {
    long i = (long)blockIdx.x * blockDim.x + threadIdx.x;
    long stride = (long)gridDim.x * blockDim.x;
    const float2* s2 = (const float2*)src;
    __half2* d2 = (__half2*)dst;
    for (; i < n2; i += stride) {
        float2 v = s2[i];
        d2[i] = __floats2half2_rn(v.x, v.y);
    }
}

// ---------------- embedding ---------------------------------------------------
__global__ void embed_kernel(const int* __restrict__ idx,
                             const float* __restrict__ wte,
                             const float* __restrict__ wpe,
                             float* __restrict__ x) {
    int m = blockIdx.x;
    int t = m % Tc;
    int row = idx[m];
    const float* wr = wte + (size_t)row * Cc;
    const float* pr = wpe + (size_t)t * Cc;
    float* xr = x + (size_t)m * Cc;
    for (int c = threadIdx.x; c < Cc; c += blockDim.x)
        xr[c] = wr[c] + pr[c];
}

// ---------------- layernorm (writes fp16; optional fp32) ----------------------
__global__ void ln_kernel(const float* __restrict__ in, __half* __restrict__ outh,
                          float* __restrict__ outf,
                          const float* __restrict__ w, const float* __restrict__ b) {
    __shared__ float sm[32];
    int m = blockIdx.x;
    const float* row = in + (size_t)m * Cc;
    float s = 0.f, ss = 0.f;
    for (int c = threadIdx.x; c < Cc; c += blockDim.x) {
        float v = row[c];
        s += v; ss += v * v;
    }
    float tot = blockSum(s, sm);
    float tot2 = blockSum(ss, sm);
    float mean = tot / Cc;
    float var = tot2 / Cc - mean * mean;
    float rstd = rsqrtf(var + EPSc);
    __half* oh = outh + (size_t)m * Cc;
    float* of = outf ? outf + (size_t)m * Cc : nullptr;
    for (int c = threadIdx.x; c < Cc; c += blockDim.x) {
        float v = (row[c] - mean) * rstd * w[c] + b[c];
        oh[c] = __float2half_rn(v);
        if (of) of[c] = v;
    }
}

// ---------------- pipelined fp16 MMA GEMM (NT): out = A @ B^T -----------------
// A: [M,K] halfs row stride ldA;  B: [N,K] halfs row stride ldB.
// Batched: z1 = z/nz2, z2 = z%nz2.
// MODE 0: +bias | 1: +bias+residual(f32) | 2: +bias+GELU | 3: plain
// OUTH: write fp16 else fp32. CAUSAL: skip tiles with bn>bm (128x128 tiles).
template <int MODE, bool OUTH, bool CAUSAL>
__global__ __launch_bounds__(256) void gemm16(
    const __half* __restrict__ A, long ldA, long aZ1, long aZ2,
    const __half* __restrict__ B, long ldB, long bZ1, long bZ2,
    const float* __restrict__ bias, const float* __restrict__ res,
    void* __restrict__ Out, long ldO, long oZ1, long oZ2,
    int K, int Nr, int nz2) {
    const int BM = 128, BN = 128, BK = 32;
    int bmB = blockIdx.y, bnB = blockIdx.x;
    if (CAUSAL && bnB > bmB) return;
    int bm = bmB * BM, bn = bnB * BN;

    int z = blockIdx.z;
    int z1 = z / nz2, z2 = z - z1 * nz2;
    A += (size_t)z1 * aZ1 + (size_t)z2 * aZ2;
    B += (size_t)z1 * bZ1 + (size_t)z2 * bZ2;
    size_t obase = (size_t)z1 * oZ1 + (size_t)z2 * oZ2;
    const float* Res = (MODE == 1) ? res + obase : nullptr;
    float*  OutF = OUTH ? nullptr : ((float*)Out + obase);
    __half* OutH = OUTH ? ((__half*)Out + obase) : nullptr;

    __shared__ __half As[2][BM][BK + 8];
    __shared__ __half Bs[2][BM][BK + 8];

    int tid = threadIdx.x;
    int lane = tid & 31;
    int wid = tid >> 5;
    int g = lane >> 2;        // 0..7
    int tq = lane & 3;        // 0..3
    int wm = (wid & 1) * 64;  // 2 warps in m
    int wn = (wid >> 1) * 32; // 4 warps in n

    // loader mapping: chunk c in [0,512): row=c>>2, k8=(c&3)*8; thread does c=tid, tid+256
    int lr = tid >> 2;         // 0..63
    int lk = (tid & 3) * 8;    // 0,8,16,24

    const __half* aP0 = A + (size_t)(bm + lr) * ldA + lk;
    const __half* aP1 = aP0 + (size_t)64 * ldA;
    int brow0 = bn + lr, brow1 = bn + lr + 64;
    int szB0 = (brow0 < Nr) ? 16 : 0;
    int szB1 = (brow1 < Nr) ? 16 : 0;
    const __half* bP0 = B + (size_t)(szB0 ? brow0 : 0) * ldB + lk;
    const __half* bP1 = B + (size_t)(szB1 ? brow1 : 0) * ldB + lk;

    float acc[4][4][4];
#pragma unroll
    for (int i = 0; i < 4; i++)
#pragma unroll
        for (int j = 0; j < 4; j++)
#pragma unroll
            for (int r = 0; r < 4; r++) acc[i][j][r] = 0.f;

    int nk = K / BK;

    // prologue: load tile 0 into buf 0
    cpasync16(&As[0][lr][lk], aP0, 16);
    cpasync16(&As[0][lr + 64][lk], aP1, 16);
    cpasync16(&Bs[0][lr][lk], bP0, szB0);
    cpasync16(&Bs[0][lr + 64][lk], bP1, szB1);
    CP_COMMIT();
    CP_WAIT0();
    __syncthreads();

    int buf = 0;
    int lrow = lane & 15;
    int lcol = (lane >> 4) * 8;

    for (int kt = 0; kt < nk; kt++) {
        if (kt + 1 < nk) {
            int k0 = (kt + 1) * BK;
            int nb = buf ^ 1;
            cpasync16(&As[nb][lr][lk], aP0 + k0, 16);
            cpasync16(&As[nb][lr + 64][lk], aP1 + k0, 16);
            cpasync16(&Bs[nb][lr][lk], bP0 + k0, szB0);
            cpasync16(&Bs[nb][lr + 64][lk], bP1 + k0, szB1);
            CP_COMMIT();
        }

#pragma unroll
        for (int kp = 0; kp < 2; kp++) {
            unsigned af[4][4];
#pragma unroll
            for (int mi = 0; mi < 4; mi++)
                ldsm4(af[mi][0], af[mi][1], af[mi][2], af[mi][3],
                      &As[buf][wm + mi * 16 + lrow][kp * 16 + lcol]);
            unsigned bf[2][4];
#pragma unroll
            for (int nb = 0; nb < 2; nb++)
                ldsm4(bf[nb][0], bf[nb][1], bf[nb][2], bf[nb][3],
                      &Bs[buf][wn + nb * 16 + lrow][kp * 16 + lcol]);
#pragma unroll
            for (int mi = 0; mi < 4; mi++)
#pragma unroll
                for (int ni = 0; ni < 4; ni++) {
                    int nb = ni >> 1, wh = ni & 1;
                    unsigned b0 = bf[nb][wh ? 1 : 0];
                    unsigned b1 = bf[nb][wh ? 3 : 2];
                    asm volatile(
                        "mma.sync.aligned.m16n8k16.row.col.f32.f16.f16.f32 "
                        "{%0,%1,%2,%3},{%4,%5,%6,%7},{%8,%9},{%0,%1,%2,%3};\n"
                        : "+f"(acc[mi][ni][0]), "+f"(acc[mi][ni][1]),
                          "+f"(acc[mi][ni][2]), "+f"(acc[mi][ni][3])
                        : "r"(af[mi][0]), "r"(af[mi][1]),
                          "r"(af[mi][2]), "r"(af[mi][3]),
                          "r"(b0), "r"(b1));
                }
        }
        if (kt + 1 < nk) CP_WAIT0();
        __syncthreads();
        buf ^= 1;
    }

    // epilogue
#pragma unroll
    for (int mi = 0; mi < 4; mi++) {
        int m = bm + wm + mi * 16 + g;
#pragma unroll
        for (int ni = 0; ni < 4; ni++) {
            int n = bn + wn + ni * 8 + tq * 2;
            if (n >= Nr) continue;
            float v0 = acc[mi][ni][0], v1 = acc[mi][ni][1];   // row m
            float v2 = acc[mi][ni][2], v3 = acc[mi][ni][3];   // row m+8
            if (MODE != 3) {
                float b0 = bias[n], b1 = bias[n + 1];
                v0 += b0; v1 += b1; v2 += b0; v3 += b1;
            }
            if (MODE == 1) {
                v0 += Res[(size_t)m * ldO + n];
                v1 += Res[(size_t)m * ldO + n + 1];
                v2 += Res[(size_t)(m + 8) * ldO + n];
                v3 += Res[(size_t)(m + 8) * ldO + n + 1];
            }
            if (MODE == 2) { v0 = geluf(v0); v1 = geluf(v1); v2 = geluf(v2); v3 = geluf(v3); }
            if (OUTH) {
                *(__half2*)(OutH + (size_t)m * ldO + n) = __floats2half2_rn(v0, v1);
                *(__half2*)(OutH + (size_t)(m + 8) * ldO + n) = __floats2half2_rn(v2, v3);
            } else {
                *(float2*)(OutF + (size_t)m * ldO + n) = make_float2(v0, v1);
                *(float2*)(OutF + (size_t)(m + 8) * ldO + n) = make_float2(v2, v3);
            }
        }
    }
}

// ---------------- causal softmax over fp16 scores ----------------------------
__global__ __launch_bounds__(256) void softmax_kernel(__half* __restrict__ S) {
    __shared__ float sm[32];
    int q = blockIdx.x;
    int z = blockIdx.y;
    __half* row = S + ((size_t)z * Tc + q) * Tc;
    const float scale = 0.125f;

    float mx = -INFINITY;
    for (int k = threadIdx.x; k <= q; k += blockDim.x)
        mx = fmaxf(mx, __half2float(row[k]) * scale);
    float MX = blockMax(mx, sm);

    float lsum = 0.f;
    for (int k = threadIdx.x; k <= q; k += blockDim.x)
        lsum += expf(__half2float(row[k]) * scale - MX);
    float SUM = blockSum(lsum, sm);
    float inv = 1.0f / SUM;
    for (int k = threadIdx.x; k < Tc; k += blockDim.x) {
        float p = (k <= q) ? expf(__half2float(row[k]) * scale - MX) * inv : 0.0f;
        row[k] = __float2half_rn(p);
    }
}

// ---------------- V transpose (fp16) -----------------------------------------
__global__ __launch_bounds__(256) void vtrans_kernel(const __half* __restrict__ qkv,
                                                     __half* __restrict__ vt) {
    __shared__ __half sh[32][72];
    int kt = blockIdx.x;
    int z = blockIdx.y;
    int b = z / Hc, h = z - b * Hc;
    const __half* base = qkv + (size_t)b * Tc * 3 * Cc + 2 * Cc + h * HDc;
    int k0 = kt * 32;
#pragma unroll
    for (int i = 0; i < 8; i++) {
        int idx = threadIdx.x + i * 256;
        int kl = idx >> 6, d = idx & 63;
        sh[kl][d] = base[(size_t)(k0 + kl) * 3 * Cc + d];
    }
    __syncthreads();
    __half* vz = vt + (size_t)z * HDc * Tc;
#pragma unroll
    for (int i = 0; i < 8; i++) {
        int idx = threadIdx.x + i * 256;
        int kl = idx & 31, d = idx >> 5;
        vz[(size_t)d * Tc + k0 + kl] = sh[kl][d];
    }
}

// ---------------- head helpers ------------------------------------------------
__global__ void ww_kernel(const float* __restrict__ wte, float* __restrict__ ww) {
    __shared__ float sm[32];
    int v = blockIdx.x;
    const float* row = wte + (size_t)v * Cc;
    float s = 0.f;
    for (int c = threadIdx.x; c < Cc; c += blockDim.x) { float t = row[c]; s += t * t; }
    float tot = blockSum(s, sm);
    if (threadIdx.x == 0) ww[v] = tot;
}
__global__ void xx_kernel(const float* __restrict__ h, float* __restrict__ xx) {
    __shared__ float sm[32];
    int m = blockIdx.x;
    const float* row = h + (size_t)m * Cc;
    float s = 0.f;
    for (int c = threadIdx.x; c < Cc; c += blockDim.x) { float t = row[c]; s += t * t; }
    float tot = blockSum(s, sm);
    if (threadIdx.x == 0) xx[m] = tot;
}

__global__ __launch_bounds__(512) void dist_kernel(float* __restrict__ out,
                                                   const float* __restrict__ ww,
                                                   const float* __restrict__ xx) {
    __shared__ float sm[32];
    int m = blockIdx.x;
    float* row = out + (size_t)m * Vc;
    float xxm = xx[m];

    float mn = INFINITY;
    for (int v = threadIdx.x; v < Vc; v += blockDim.x) {
        float d = ww[v] + xxm - 2.0f * row[v];
        mn = fminf(mn, d);
    }
    float MN = blockMin(mn, sm);

    float lsum = 0.f;
    for (int v = threadIdx.x; v < Vc; v += blockDim.x) {
        float d = ww[v] + xxm - 2.0f * row[v];
        float r = d / MN;
        float p = expf(-768.0f * logf(r));
        if (!isfinite(p)) p = 0.0f;
        row[v] = p;
        lsum += p;
    }
    float TOT = blockSum(lsum, sm);
    float invTot = 1.0f / TOT;
    const float floorp = 0.01f / 50304.0f;

    for (int v = threadIdx.x; v < Vc; v += blockDim.x)
        row[v] = logf(row[v] * invTot + floorp);
}

// ---------------- launch ------------------------------------------------------
extern "C" void kernel_launch(void* const* d_in, const int* in_sizes, int n_in,
                              void* d_out, int out_size) {
    const int*   idx    = (const int*)d_in[0];
    const float* wte    = (const float*)d_in[1];
    const float* wpe    = (const float*)d_in[2];
    const float* ln1_w  = (const float*)d_in[3];
    const float* ln1_b  = (const float*)d_in[4];
    const float* attn_w = (const float*)d_in[5];
    const float* attn_b = (const float*)d_in[6];
    const float* proj_w = (const float*)d_in[7];
    const float* proj_b = (const float*)d_in[8];
    const float* ln2_w  = (const float*)d_in[9];
    const float* ln2_b  = (const float*)d_in[10];
    const float* fc_w   = (const float*)d_in[11];
    const float* fc_b   = (const float*)d_in[12];
    const float* fc2_w  = (const float*)d_in[13];
    const float* fc2_b  = (const float*)d_in[14];
    const float* lnf_w  = (const float*)d_in[15];
    const float* lnf_b  = (const float*)d_in[16];
    float* out = (float*)d_out;

    float *x, *hf, *ww, *xx;
    __half *attn16, *proj16, *fcw16, *fc2w16, *wte16;
    __half *h16, *qkv16, *y16, *fcact16, *s16, *vt16;
    cudaGetSymbolAddress((void**)&x, g_x);
    cudaGetSymbolAddress((void**)&hf, g_hf);
    cudaGetSymbolAddress((void**)&ww, g_ww);
    cudaGetSymbolAddress((void**)&xx, g_xx);
    cudaGetSymbolAddress((void**)&attn16, w_attn16);
    cudaGetSymbolAddress((void**)&proj16, w_proj16);
    cudaGetSymbolAddress((void**)&fcw16, w_fc16);
    cudaGetSymbolAddress((void**)&fc2w16, w_fc216);
    cudaGetSymbolAddress((void**)&wte16, w_wte16);
    cudaGetSymbolAddress((void**)&h16, g_h16);
    cudaGetSymbolAddress((void**)&qkv16, g_qkv16);
    cudaGetSymbolAddress((void**)&y16, g_y16);
    cudaGetSymbolAddress((void**)&fcact16, g_fc16);
    cudaGetSymbolAddress((void**)&s16, g_s16);
    cudaGetSymbolAddress((void**)&vt16, g_vt16);

    // weight conversions
    f2h_kernel<<<4096, 256>>>(attn_w, attn16, (long)Lc * 3 * Cc * Cc / 2);
    f2h_kernel<<<4096, 256>>>(proj_w, proj16, (long)Lc * Cc * Cc / 2);
    f2h_kernel<<<4096, 256>>>(fc_w, fcw16, (long)Lc * 4 * Cc * Cc / 2);
    f2h_kernel<<<4096, 256>>>(fc2_w, fc2w16, (long)Lc * Cc * 4 * Cc / 2);
    f2h_kernel<<<4096, 256>>>(wte, wte16, (long)Vc * Cc / 2);

    embed_kernel<<<Mc, 256>>>(idx, wte, wpe, x);
    ww_kernel<<<Vc, 128>>>(wte, ww);

    const long S3C = 3 * Cc;
    for (int l = 0; l < Lc; l++) {
        const float* l1w = ln1_w + (size_t)l * Cc;
        const float* l1b = ln1_b + (size_t)l * Cc;
        const __half* aw = attn16 + (size_t)l * 3 * Cc * Cc;
        const float* ab  = attn_b + (size_t)l * 3 * Cc;
        const __half* pw = proj16 + (size_t)l * Cc * Cc;
        const float* pb  = proj_b + (size_t)l * Cc;
        const float* l2w = ln2_w + (size_t)l * Cc;
        const float* l2b = ln2_b + (size_t)l * Cc;
        const __half* fw = fcw16 + (size_t)l * 4 * Cc * Cc;
        const float* fb  = fc_b + (size_t)l * 4 * Cc;
        const __half* f2w = fc2w16 + (size_t)l * Cc * 4 * Cc;
        const float* f2b = fc2_b + (size_t)l * Cc;

        ln_kernel<<<Mc, 256>>>(x, h16, nullptr, l1w, l1b);

        // qkv16 = h @ attn_w^T + b   [1024, 2304]
        gemm16<0, true, false><<<dim3(18, 8, 1), 256>>>(
            h16, Cc, 0, 0, aw, Cc, 0, 0, ab, nullptr,
            qkv16, S3C, 0, 0, Cc, 3 * Cc, 1);

        // S = Q @ K^T (batched z=b*H+h, causal tile skip)
        gemm16<3, true, true><<<dim3(4, 4, BHc), 256>>>(
            qkv16, S3C, (long)Tc * S3C, HDc,
            qkv16 + Cc, S3C, (long)Tc * S3C, HDc,
            nullptr, nullptr,
            s16, Tc, (long)Hc * Tc * Tc, (long)Tc * Tc, HDc, Tc, Hc);

        softmax_kernel<<<dim3(Tc, BHc), 256>>>(s16);
        vtrans_kernel<<<dim3(Tc / 32, BHc), 256>>>(qkv16, vt16);

        // y16 = P @ V^T
        gemm16<3, true, false><<<dim3(1, 4, BHc), 256>>>(
            s16, Tc, (long)Hc * Tc * Tc, (long)Tc * Tc,
            vt16, Tc, (long)Hc * HDc * Tc, (long)HDc * Tc,
            nullptr, nullptr,
            y16, Cc, (long)Tc * Cc, HDc, Tc, HDc, Hc);

        // x = x + y @ proj_w^T + proj_b   (fp32 out)
        gemm16<1, false, false><<<dim3(6, 8, 1), 256>>>(
            y16, Cc, 0, 0, pw, Cc, 0, 0, pb, x,
            x, Cc, 0, 0, Cc, Cc, 1);

        ln_kernel<<<Mc, 256>>>(x, h16, nullptr, l2w, l2b);

        // fc16 = gelu(h @ fc_w^T + fc_b)  [1024, 3072]
        gemm16<2, true, false><<<dim3(24, 8, 1), 256>>>(
            h16, Cc, 0, 0, fw, Cc, 0, 0, fb, nullptr,
            fcact16, 4 * Cc, 0, 0, Cc, 4 * Cc, 1);

        // x = x + fc @ fc2_w^T + fc2_b
        gemm16<1, false, false><<<dim3(6, 8, 1), 256>>>(
            fcact16, 4 * Cc, 0, 0, f2w, 4 * Cc, 0, 0, f2b, x,
            x, Cc, 0, 0, 4 * Cc, Cc, 1);
    }

    // final LN (fp16 + fp32 copies) + head
    ln_kernel<<<Mc, 256>>>(x, h16, hf, lnf_w, lnf_b);
    xx_kernel<<<Mc, 256>>>(hf, xx);

    // wx = h @ wte^T  [1024, 50304] (fp32 out)
    gemm16<3, false, false><<<dim3(Vc / 128, 8, 1), 256>>>(
        h16, Cc, 0, 0, wte16, Cc, 0, 0, nullptr, nullptr,
        out, Vc, 0, 0, Cc, Vc, 1);

    dist_kernel<<<Mc, 512>>>(out, ww, xx);
}

// round 7
// speedup vs baseline: 7.5661x; 1.3173x over previous
#include <cuda_runtime.h>
#include <cuda_fp16.h>
#include <math.h>
#include <stdint.h>

// Problem constants
#define Bc   2
#define Tc   512
#define Cc   768
#define Hc   12
#define HDc  64
#define Vc   50304
#define Lc   12
#define Mc   (Bc * Tc)          // 1024 rows
#define BHc  (Bc * Hc)          // 24
#define EPSc 1e-5f
#define GELU_Kc 0.7978845608028654f

// ---------------- scratch (device globals; no allocations allowed) ----------
__device__ float  g_x[Mc * Cc];
__device__ float  g_ww[Vc];
__device__ float  g_xx[Mc];

__device__ __half w_attn16[Lc * 3 * Cc * Cc];
__device__ __half w_proj16[Lc * Cc * Cc];
__device__ __half w_fc16[Lc * 4 * Cc * Cc];
__device__ __half w_fc216[Lc * Cc * 4 * Cc];
__device__ __half w_wte16[(size_t)Vc * Cc];

__device__ __half g_h16[Mc * Cc];
__device__ __half g_qkv16[Mc * 3 * Cc];
__device__ __half g_y16[Mc * Cc];
__device__ __half g_fc16[Mc * 4 * Cc];

// ---------------- reduction helpers -----------------------------------------
__device__ __forceinline__ float warpSum(float v) {
#pragma unroll
    for (int o = 16; o; o >>= 1) v += __shfl_xor_sync(0xffffffffu, v, o);
    return v;
}
__device__ __forceinline__ float warpMin(float v) {
#pragma unroll
    for (int o = 16; o; o >>= 1) v = fminf(v, __shfl_xor_sync(0xffffffffu, v, o));
    return v;
}
__device__ float blockSum(float v, float* sm) {
    int lane = threadIdx.x & 31, wid = threadIdx.x >> 5;
    int nw = blockDim.x >> 5;
    v = warpSum(v);
    if (lane == 0) sm[wid] = v;
    __syncthreads();
    float r = (threadIdx.x < nw) ? sm[threadIdx.x] : 0.0f;
    if (wid == 0) { r = warpSum(r); if (lane == 0) sm[0] = r; }
    __syncthreads();
    float out = sm[0];
    __syncthreads();
    return out;
}
__device__ float blockMin(float v, float* sm) {
    int lane = threadIdx.x & 31, wid = threadIdx.x >> 5;
    int nw = blockDim.x >> 5;
    v = warpMin(v);
    if (lane == 0) sm[wid] = v;
    __syncthreads();
    float r = (threadIdx.x < nw) ? sm[threadIdx.x] : INFINITY;
    if (wid == 0) { r = warpMin(r); if (lane == 0) sm[0] = r; }
    __syncthreads();
    float out = sm[0];
    __syncthreads();
    return out;
}

// ---------------- low-level asm helpers --------------------------------------
__device__ __forceinline__ void cpasync16(void* smem, const void* g, int sz) {
    unsigned a = (unsigned)__cvta_generic_to_shared(smem);
    asm volatile("cp.async.cg.shared.global [%0], [%1], 16, %2;\n"
                 :: "r"(a), "l"(g), "r"(sz));
}
#define CP_COMMIT() asm volatile("cp.async.commit_group;\n")
#define CP_WAIT0()  asm volatile("cp.async.wait_group 0;\n")
#define CP_WAIT1()  asm volatile("cp.async.wait_group 1;\n")

__device__ __forceinline__ void ldsm4(unsigned& r0, unsigned& r1, unsigned& r2,
                                      unsigned& r3, const __half* p) {
    unsigned a = (unsigned)__cvta_generic_to_shared(p);
    asm volatile("ldmatrix.sync.aligned.m8n8.x4.shared.b16 {%0,%1,%2,%3}, [%4];\n"
                 : "=r"(r0), "=r"(r1), "=r"(r2), "=r"(r3) : "r"(a));
}
__device__ __forceinline__ void ldsm4t(unsigned& r0, unsigned& r1, unsigned& r2,
                                       unsigned& r3, const __half* p) {
    unsigned a = (unsigned)__cvta_generic_to_shared(p);
    asm volatile("ldmatrix.sync.aligned.m8n8.x4.trans.shared.b16 {%0,%1,%2,%3}, [%4];\n"
                 : "=r"(r0), "=r"(r1), "=r"(r2), "=r"(r3) : "r"(a));
}
__device__ __forceinline__ void mma16(float* c, unsigned a0, unsigned a1,
                                      unsigned a2, unsigned a3,
                                      unsigned b0, unsigned b1) {
    asm volatile(
        "mma.sync.aligned.m16n8k16.row.col.f32.f16.f16.f32 "
        "{%0,%1,%2,%3},{%4,%5,%6,%7},{%8,%9},{%0,%1,%2,%3};\n"
        : "+f"(c[0]), "+f"(c[1]), "+f"(c[2]), "+f"(c[3])
        : "r"(a0), "r"(a1), "r"(a2), "r"(a3), "r"(b0), "r"(b1));
}

__device__ __forceinline__ float geluf(float t) {
    return 0.5f * t * (1.0f + tanhf(GELU_Kc * (t + 0.044715f * t * t * t)));
}

// ---------------- f32 -> f16 convert ------------------------------------------
__global__ void f2h_kernel(const float* __restrict__ src, __half* __restrict__ dst,
                           long n2) {
    long i = (long)blockIdx.x * blockDim.x + threadIdx.x;
    long stride = (long)gridDim.x * blockDim.x;
    const float2* s2 = (const float2*)src;
    __half2* d2 = (__half2*)dst;
    for (; i < n2; i += stride) {
        float2 v = s2[i];
        d2[i] = __floats2half2_rn(v.x, v.y);
    }
}

// ---------------- embedding ---------------------------------------------------
__global__ void embed_kernel(const int* __restrict__ idx,
                             const float* __restrict__ wte,
                             const float* __restrict__ wpe,
                             float* __restrict__ x) {
    int m = blockIdx.x;
    int t = m % Tc;
    int row = idx[m];
    const float* wr = wte + (size_t)row * Cc;
    const float* pr = wpe + (size_t)t * Cc;
    float* xr = x + (size_t)m * Cc;
    for (int c = threadIdx.x; c < Cc; c += blockDim.x)
        xr[c] = wr[c] + pr[c];
}

// ---------------- layernorm (fp16 out; optional fused sum-sq) -----------------
__global__ void ln_kernel(const float* __restrict__ in, __half* __restrict__ outh,
                          float* __restrict__ xx,
                          const float* __restrict__ w, const float* __restrict__ b) {
    __shared__ float sm[32];
    int m = blockIdx.x;
    const float* row = in + (size_t)m * Cc;
    float s = 0.f, ss = 0.f;
    for (int c = threadIdx.x; c < Cc; c += blockDim.x) {
        float v = row[c];
        s += v; ss += v * v;
    }
    float tot = blockSum(s, sm);
    float tot2 = blockSum(ss, sm);
    float mean = tot / Cc;
    float var = tot2 / Cc - mean * mean;
    float rstd = rsqrtf(var + EPSc);
    __half* oh = outh + (size_t)m * Cc;
    float s2 = 0.f;
    for (int c = threadIdx.x; c < Cc; c += blockDim.x) {
        float v = (row[c] - mean) * rstd * w[c] + b[c];
        oh[c] = __float2half_rn(v);
        s2 += v * v;
    }
    if (xx) {
        float t2 = blockSum(s2, sm);
        if (threadIdx.x == 0) xx[m] = t2;
    }
}

// ---------------- 3-stage pipelined fp16 MMA GEMM (NT): out = A @ B^T ---------
// MODE 0: +bias | 1: +bias+residual(f32) | 2: +bias+GELU | 3: plain
// OUTH: write fp16 else fp32.  BN: 128 or 64.
template <int MODE, bool OUTH, int BN>
__global__ __launch_bounds__(256) void gemm16(
    const __half* __restrict__ A, long ldA,
    const __half* __restrict__ B, long ldB,
    const float* __restrict__ bias, const float* __restrict__ res,
    void* __restrict__ Out, long ldO,
    int K, int Nr) {
    const int BM = 128, BK = 32, BK8 = BK + 8;
    const int NI = BN / 32;          // n8 tiles per warp
    const int NB = NI / 2;           // n16 ldsm groups per warp
    int bm = blockIdx.y * BM;
    int bn = blockIdx.x * BN;

    extern __shared__ unsigned char dyn_raw[];
    __half* As = (__half*)dyn_raw;                         // [3][BM][BK8]
    __half* Bs = As + 3 * BM * BK8;                        // [3][BN][BK8]
#define ASM_(s, r, c) As[((s) * BM + (r)) * BK8 + (c)]
#define BSM_(s, r, c) Bs[((s) * BN + (r)) * BK8 + (c)]

    const float* Res = (MODE == 1) ? res : nullptr;
    float*  OutF = OUTH ? nullptr : (float*)Out;
    __half* OutH = OUTH ? (__half*)Out : nullptr;

    int tid = threadIdx.x;
    int lane = tid & 31;
    int wid = tid >> 5;
    int g = lane >> 2;
    int tq = lane & 3;
    int wm = (wid & 1) * 64;
    int wn = (wid >> 1) * (NI * 8);   // FIX: each warp owns NI*8 columns
    int lrow = lane & 15;
    int lcol = (lane >> 4) * 8;

    int lr = tid >> 2;         // 0..63
    int lk = (tid & 3) * 8;

    const __half* aP0 = A + (size_t)(bm + lr) * ldA + lk;
    const __half* aP1 = aP0 + (size_t)64 * ldA;
    int brow0 = bn + lr, brow1 = bn + lr + 64;
    int szB0 = (brow0 < Nr) ? 16 : 0;
    int szB1 = (brow1 < Nr) ? 16 : 0;
    const __half* bP0 = B + (size_t)(szB0 ? brow0 : 0) * ldB + lk;
    const __half* bP1 = B + (size_t)(szB1 ? brow1 : 0) * ldB + lk;

    float acc[4][NI][4];
#pragma unroll
    for (int i = 0; i < 4; i++)
#pragma unroll
        for (int j = 0; j < NI; j++)
#pragma unroll
            for (int r = 0; r < 4; r++) acc[i][j][r] = 0.f;

    int nk = K / BK;

    auto load_tile = [&](int st, int kt) {
        int k0 = kt * BK;
        cpasync16(&ASM_(st, lr, lk), aP0 + k0, 16);
        cpasync16(&ASM_(st, lr + 64, lk), aP1 + k0, 16);
        cpasync16(&BSM_(st, lr, lk), bP0 + k0, szB0);
        if (BN == 128) cpasync16(&BSM_(st, lr + 64, lk), bP1 + k0, szB1);
        CP_COMMIT();
    };

    // prologue: 2 tiles in flight
    load_tile(0, 0);
    if (nk > 1) load_tile(1, 1);

    for (int kt = 0; kt < nk; kt++) {
        if (kt + 1 < nk) { CP_WAIT1(); } else { CP_WAIT0(); }
        __syncthreads();
        if (kt + 2 < nk) load_tile((kt + 2) % 3, kt + 2);
        int buf = kt % 3;

#pragma unroll
        for (int kp = 0; kp < 2; kp++) {
            unsigned af[4][4];
#pragma unroll
            for (int mi = 0; mi < 4; mi++)
                ldsm4(af[mi][0], af[mi][1], af[mi][2], af[mi][3],
                      &ASM_(buf, wm + mi * 16 + lrow, kp * 16 + lcol));
            unsigned bf[NB][4];
#pragma unroll
            for (int nb = 0; nb < NB; nb++)
                ldsm4(bf[nb][0], bf[nb][1], bf[nb][2], bf[nb][3],
                      &BSM_(buf, wn + nb * 16 + lrow, kp * 16 + lcol));
#pragma unroll
            for (int mi = 0; mi < 4; mi++)
#pragma unroll
                for (int ni = 0; ni < NI; ni++) {
                    int nb = ni >> 1, wh = ni & 1;
                    mma16(acc[mi][ni],
                          af[mi][0], af[mi][1], af[mi][2], af[mi][3],
                          bf[nb][wh ? 1 : 0], bf[nb][wh ? 3 : 2]);
                }
        }
        __syncthreads();
    }

    // epilogue
#pragma unroll
    for (int mi = 0; mi < 4; mi++) {
        int m = bm + wm + mi * 16 + g;
#pragma unroll
        for (int ni = 0; ni < NI; ni++) {
            int n = bn + wn + ni * 8 + tq * 2;
            if (n >= Nr) continue;
            float v0 = acc[mi][ni][0], v1 = acc[mi][ni][1];
            float v2 = acc[mi][ni][2], v3 = acc[mi][ni][3];
            if (MODE != 3) {
                float b0 = bias[n], b1 = bias[n + 1];
                v0 += b0; v1 += b1; v2 += b0; v3 += b1;
            }
            if (MODE == 1) {
                v0 += Res[(size_t)m * ldO + n];
                v1 += Res[(size_t)m * ldO + n + 1];
                v2 += Res[(size_t)(m + 8) * ldO + n];
                v3 += Res[(size_t)(m + 8) * ldO + n + 1];
            }
            if (MODE == 2) { v0 = geluf(v0); v1 = geluf(v1); v2 = geluf(v2); v3 = geluf(v3); }
            if (OUTH) {
                *(__half2*)(OutH + (size_t)m * ldO + n) = __floats2half2_rn(v0, v1);
                *(__half2*)(OutH + (size_t)(m + 8) * ldO + n) = __floats2half2_rn(v2, v3);
            } else {
                *(float2*)(OutF + (size_t)m * ldO + n) = make_float2(v0, v1);
                *(float2*)(OutF + (size_t)(m + 8) * ldO + n) = make_float2(v2, v3);
            }
        }
    }
#undef ASM_
#undef BSM_
}

// ---------------- fused flash attention ---------------------------------------
// One block per (q-tile of 64, b*H+h). 128 threads, 4 warps; warp w owns rows
// w*16..w*16+15 of the Q tile. Online softmax; K/V tiles double-buffered.
__global__ __launch_bounds__(128) void flash_kernel(const __half* __restrict__ qkv,
                                                    __half* __restrict__ y) {
    int qt = blockIdx.x, z = blockIdx.y;
    int b = z / Hc, h = z - b * Hc;
    const __half* base = qkv + (size_t)b * Tc * 3 * Cc;
    const __half* Qg = base + (size_t)qt * 64 * 3 * Cc + h * HDc;
    const __half* Kg = base + Cc + h * HDc;
    const __half* Vg = base + 2 * Cc + h * HDc;

    __shared__ __half Qs[64][72];
    __shared__ __half Ks[2][64][72];
    __shared__ __half Vs[2][64][72];

    int tid = threadIdx.x, lane = tid & 31, w = tid >> 5;
    int g = lane >> 2, tq = lane & 3;
    int lrow = lane & 15, lcol = (lane >> 4) * 8;

    // load Q tile + K/V tile 0 (one group)
    for (int c = tid; c < 512; c += 128) {
        int r = c >> 3, c8 = (c & 7) * 8;
        cpasync16(&Qs[r][c8], Qg + (size_t)r * 3 * Cc + c8, 16);
        cpasync16(&Ks[0][r][c8], Kg + (size_t)r * 3 * Cc + c8, 16);
        cpasync16(&Vs[0][r][c8], Vg + (size_t)r * 3 * Cc + c8, 16);
    }
    CP_COMMIT();
    CP_WAIT0();
    __syncthreads();

    unsigned qf[4][4];
#pragma unroll
    for (int kc = 0; kc < 4; kc++)
        ldsm4(qf[kc][0], qf[kc][1], qf[kc][2], qf[kc][3],
              &Qs[w * 16 + lrow][kc * 16 + lcol]);

    float o[8][4];
#pragma unroll
    for (int i = 0; i < 8; i++)
#pragma unroll
        for (int r = 0; r < 4; r++) o[i][r] = 0.f;
    float m0 = -INFINITY, m1 = -INFINITY, l0 = 0.f, l1 = 0.f;

    int buf = 0;
    for (int j = 0; j <= qt; j++) {
        if (j + 1 <= qt) {
            for (int c = tid; c < 512; c += 128) {
                int r = c >> 3, c8 = (c & 7) * 8;
                cpasync16(&Ks[buf ^ 1][r][c8],
                          Kg + (size_t)((j + 1) * 64 + r) * 3 * Cc + c8, 16);
                cpasync16(&Vs[buf ^ 1][r][c8],
                          Vg + (size_t)((j + 1) * 64 + r) * 3 * Cc + c8, 16);
            }
            CP_COMMIT();
            CP_WAIT1();
        } else {
            CP_WAIT0();
        }
        __syncthreads();

        // S = Q @ K^T (64x64 per block, this warp: 16x64)
        float s[8][4];
#pragma unroll
        for (int i = 0; i < 8; i++)
#pragma unroll
            for (int r = 0; r < 4; r++) s[i][r] = 0.f;
#pragma unroll
        for (int kc = 0; kc < 4; kc++) {
            unsigned kf[4][4];
#pragma unroll
            for (int nb = 0; nb < 4; nb++)
                ldsm4(kf[nb][0], kf[nb][1], kf[nb][2], kf[nb][3],
                      &Ks[buf][nb * 16 + lrow][kc * 16 + lcol]);
#pragma unroll
            for (int nb = 0; nb < 4; nb++) {
                mma16(s[nb * 2], qf[kc][0], qf[kc][1], qf[kc][2], qf[kc][3],
                      kf[nb][0], kf[nb][2]);
                mma16(s[nb * 2 + 1], qf[kc][0], qf[kc][1], qf[kc][2], qf[kc][3],
                      kf[nb][1], kf[nb][3]);
            }
        }
        // scale + causal mask (diagonal tile only)
#pragma unroll
        for (int i = 0; i < 8; i++)
#pragma unroll
            for (int r = 0; r < 4; r++) s[i][r] *= 0.125f;
        if (j == qt) {
            int r0 = w * 16 + g, r1 = r0 + 8;
#pragma unroll
            for (int nt = 0; nt < 8; nt++) {
                int c0 = nt * 8 + tq * 2;
                if (c0 > r0) s[nt][0] = -1e30f;
                if (c0 + 1 > r0) s[nt][1] = -1e30f;
                if (c0 > r1) s[nt][2] = -1e30f;
                if (c0 + 1 > r1) s[nt][3] = -1e30f;
            }
        }
        // row max (this tile)
        float tm0 = -INFINITY, tm1 = -INFINITY;
#pragma unroll
        for (int nt = 0; nt < 8; nt++) {
            tm0 = fmaxf(tm0, fmaxf(s[nt][0], s[nt][1]));
            tm1 = fmaxf(tm1, fmaxf(s[nt][2], s[nt][3]));
        }
        tm0 = fmaxf(tm0, __shfl_xor_sync(0xffffffffu, tm0, 1));
        tm0 = fmaxf(tm0, __shfl_xor_sync(0xffffffffu, tm0, 2));
        tm1 = fmaxf(tm1, __shfl_xor_sync(0xffffffffu, tm1, 1));
        tm1 = fmaxf(tm1, __shfl_xor_sync(0xffffffffu, tm1, 2));
        float mn0 = fmaxf(m0, tm0), mn1 = fmaxf(m1, tm1);
        float a0 = __expf(m0 - mn0), a1 = __expf(m1 - mn1);
        m0 = mn0; m1 = mn1;

        float rs0 = 0.f, rs1 = 0.f;
        unsigned pa[4][4];
#pragma unroll
        for (int nt = 0; nt < 8; nt++) {
            float p0 = __expf(s[nt][0] - mn0);
            float p1 = __expf(s[nt][1] - mn0);
            float p2 = __expf(s[nt][2] - mn1);
            float p3 = __expf(s[nt][3] - mn1);
            rs0 += p0 + p1; rs1 += p2 + p3;
            int kc2 = nt >> 1, hh = (nt & 1) * 2;
            __half2 h01 = __floats2half2_rn(p0, p1);
            __half2 h23 = __floats2half2_rn(p2, p3);
            pa[kc2][hh]     = *(unsigned*)&h01;
            pa[kc2][hh + 1] = *(unsigned*)&h23;
        }
        rs0 += __shfl_xor_sync(0xffffffffu, rs0, 1);
        rs0 += __shfl_xor_sync(0xffffffffu, rs0, 2);
        rs1 += __shfl_xor_sync(0xffffffffu, rs1, 1);
        rs1 += __shfl_xor_sync(0xffffffffu, rs1, 2);
        l0 = l0 * a0 + rs0;
        l1 = l1 * a1 + rs1;
#pragma unroll
        for (int nt = 0; nt < 8; nt++) {
            o[nt][0] *= a0; o[nt][1] *= a0;
            o[nt][2] *= a1; o[nt][3] *= a1;
        }
        // O += P @ V   (V fragments via ldmatrix.trans)
#pragma unroll
        for (int kc2 = 0; kc2 < 4; kc2++) {
#pragma unroll
            for (int dn = 0; dn < 4; dn++) {
                unsigned v0, v1, v2, v3;
                ldsm4t(v0, v1, v2, v3,
                       &Vs[buf][kc2 * 16 + lrow][dn * 16 + lcol]);
                mma16(o[dn * 2], pa[kc2][0], pa[kc2][1], pa[kc2][2], pa[kc2][3], v0, v1);
                mma16(o[dn * 2 + 1], pa[kc2][0], pa[kc2][1], pa[kc2][2], pa[kc2][3], v2, v3);
            }
        }
        __syncthreads();
        buf ^= 1;
    }

    float il0 = 1.0f / l0, il1 = 1.0f / l1;
    int row0 = qt * 64 + w * 16 + g;
    __half* yp = y + ((size_t)(b * Tc + row0)) * Cc + h * HDc;
#pragma unroll
    for (int nt = 0; nt < 8; nt++) {
        int col = nt * 8 + tq * 2;
        *(__half2*)(yp + col) = __floats2half2_rn(o[nt][0] * il0, o[nt][1] * il0);
        *(__half2*)(yp + (size_t)8 * Cc + col) =
            __floats2half2_rn(o[nt][2] * il1, o[nt][3] * il1);
    }
}

// ---------------- head helpers ------------------------------------------------
__global__ void ww_kernel(const float* __restrict__ wte, float* __restrict__ ww) {
    __shared__ float sm[32];
    int v = blockIdx.x;
    const float* row = wte + (size_t)v * Cc;
    float s = 0.f;
    for (int c = threadIdx.x; c < Cc; c += blockDim.x) { float t = row[c]; s += t * t; }
    float tot = blockSum(s, sm);
    if (threadIdx.x == 0) ww[v] = tot;
}

__global__ __launch_bounds__(512) void dist_kernel(float* __restrict__ out,
                                                   const float* __restrict__ ww,
                                                   const float* __restrict__ xx) {
    __shared__ float sm[32];
    int m = blockIdx.x;
    float* row = out + (size_t)m * Vc;
    float xxm = xx[m];

    float mn = INFINITY;
    for (int v = threadIdx.x; v < Vc; v += blockDim.x) {
        float d = ww[v] + xxm - 2.0f * row[v];
        mn = fminf(mn, d);
    }
    float MN = blockMin(mn, sm);
    float iMN = 1.0f / MN;

    float lsum = 0.f;
    for (int v = threadIdx.x; v < Vc; v += blockDim.x) {
        float d = ww[v] + xxm - 2.0f * row[v];
        float r = d * iMN;
        float p = exp2f(-768.0f * __log2f(r));
        if (!isfinite(p)) p = 0.0f;
        row[v] = p;
        lsum += p;
    }
    float TOT = blockSum(lsum, sm);
    float invTot = 1.0f / TOT;
    const float floorp = 0.01f / 50304.0f;

    for (int v = threadIdx.x; v < Vc; v += blockDim.x)
        row[v] = __logf(row[v] * invTot + floorp);
}

// ---------------- launch ------------------------------------------------------
extern "C" void kernel_launch(void* const* d_in, const int* in_sizes, int n_in,
                              void* d_out, int out_size) {
    const int*   idx    = (const int*)d_in[0];
    const float* wte    = (const float*)d_in[1];
    const float* wpe    = (const float*)d_in[2];
    const float* ln1_w  = (const float*)d_in[3];
    const float* ln1_b  = (const float*)d_in[4];
    const float* attn_w = (const float*)d_in[5];
    const float* attn_b = (const float*)d_in[6];
    const float* proj_w = (const float*)d_in[7];
    const float* proj_b = (const float*)d_in[8];
    const float* ln2_w  = (const float*)d_in[9];
    const float* ln2_b  = (const float*)d_in[10];
    const float* fc_w   = (const float*)d_in[11];
    const float* fc_b   = (const float*)d_in[12];
    const float* fc2_w  = (const float*)d_in[13];
    const float* fc2_b  = (const float*)d_in[14];
    const float* lnf_w  = (const float*)d_in[15];
    const float* lnf_b  = (const float*)d_in[16];
    float* out = (float*)d_out;

    float *x, *ww, *xx;
    __half *attn16, *proj16, *fcw16, *fc2w16, *wte16;
    __half *h16, *qkv16, *y16, *fcact16;
    cudaGetSymbolAddress((void**)&x, g_x);
    cudaGetSymbolAddress((void**)&ww, g_ww);
    cudaGetSymbolAddress((void**)&xx, g_xx);
    cudaGetSymbolAddress((void**)&attn16, w_attn16);
    cudaGetSymbolAddress((void**)&proj16, w_proj16);
    cudaGetSymbolAddress((void**)&fcw16, w_fc16);
    cudaGetSymbolAddress((void**)&fc2w16, w_fc216);
    cudaGetSymbolAddress((void**)&wte16, w_wte16);
    cudaGetSymbolAddress((void**)&h16, g_h16);
    cudaGetSymbolAddress((void**)&qkv16, g_qkv16);
    cudaGetSymbolAddress((void**)&y16, g_y16);
    cudaGetSymbolAddress((void**)&fcact16, g_fc16);

    const int SM128 = 3 * 128 * 40 * 2 * 2;          // 61440 bytes
    const int SM64  = (3 * 128 * 40 + 3 * 64 * 40) * 2;  // 46080 bytes
    cudaFuncSetAttribute(gemm16<0, true, 128>,
                         cudaFuncAttributeMaxDynamicSharedMemorySize, SM128);
    cudaFuncSetAttribute(gemm16<2, true, 128>,
                         cudaFuncAttributeMaxDynamicSharedMemorySize, SM128);
    cudaFuncSetAttribute(gemm16<3, false, 128>,
                         cudaFuncAttributeMaxDynamicSharedMemorySize, SM128);
    cudaFuncSetAttribute(gemm16<1, false, 64>,
                         cudaFuncAttributeMaxDynamicSharedMemorySize, SM64);

    // weight conversions
    f2h_kernel<<<4096, 256>>>(attn_w, attn16, (long)Lc * 3 * Cc * Cc / 2);
    f2h_kernel<<<4096, 256>>>(proj_w, proj16, (long)Lc * Cc * Cc / 2);
    f2h_kernel<<<4096, 256>>>(fc_w, fcw16, (long)Lc * 4 * Cc * Cc / 2);
    f2h_kernel<<<4096, 256>>>(fc2_w, fc2w16, (long)Lc * Cc * 4 * Cc / 2);
    f2h_kernel<<<4096, 256>>>(wte, wte16, (long)Vc * Cc / 2);

    embed_kernel<<<Mc, 256>>>(idx, wte, wpe, x);
    ww_kernel<<<Vc, 128>>>(wte, ww);

    for (int l = 0; l < Lc; l++) {
        const float* l1w = ln1_w + (size_t)l * Cc;
        const float* l1b = ln1_b + (size_t)l * Cc;
        const __half* aw = attn16 + (size_t)l * 3 * Cc * Cc;
        const float* ab  = attn_b + (size_t)l * 3 * Cc;
        const __half* pw = proj16 + (size_t)l * Cc * Cc;
        const float* pb  = proj_b + (size_t)l * Cc;
        const float* l2w = ln2_w + (size_t)l * Cc;
        const float* l2b = ln2_b + (size_t)l * Cc;
        const __half* fw = fcw16 + (size_t)l * 4 * Cc * Cc;
        const float* fb  = fc_b + (size_t)l * 4 * Cc;
        const __half* f2w = fc2w16 + (size_t)l * Cc * 4 * Cc;
        const float* f2b = fc2_b + (size_t)l * Cc;

        ln_kernel<<<Mc, 256>>>(x, h16, nullptr, l1w, l1b);

        // qkv16 = h @ attn_w^T + b   [1024, 2304]
        gemm16<0, true, 128><<<dim3(18, 8), 256, SM128>>>(
            h16, Cc, aw, Cc, ab, nullptr, qkv16, 3 * Cc, Cc, 3 * Cc);

        // fused attention -> y16
        flash_kernel<<<dim3(8, BHc), 128>>>(qkv16, y16);

        // x = x + y @ proj_w^T + proj_b   (fp32 out)
        gemm16<1, false, 64><<<dim3(12, 8), 256, SM64>>>(
            y16, Cc, pw, Cc, pb, x, x, Cc, Cc, Cc);

        ln_kernel<<<Mc, 256>>>(x, h16, nullptr, l2w, l2b);

        // fc16 = gelu(h @ fc_w^T + fc_b)  [1024, 3072]
        gemm16<2, true, 128><<<dim3(24, 8), 256, SM128>>>(
            h16, Cc, fw, Cc, fb, nullptr, fcact16, 4 * Cc, Cc, 4 * Cc);

        // x = x + fc @ fc2_w^T + fc2_b
        gemm16<1, false, 64><<<dim3(12, 8), 256, SM64>>>(
            fcact16, 4 * Cc, f2w, 4 * Cc, f2b, x, x, Cc, 4 * Cc, Cc);
    }

    // final LN (+ fused xx) + head
    ln_kernel<<<Mc, 256>>>(x, h16, xx, lnf_w, lnf_b);

    // wx = h @ wte^T  [1024, 50304] (fp32 out)
    gemm16<3, false, 128><<<dim3(Vc / 128, 8), 256, SM128>>>(
        h16, Cc, wte16, Cc, nullptr, nullptr, out, Vc, Cc, Vc);

    dist_kernel<<<Mc, 512>>>(out, ww, xx);
}

// round 10
// speedup vs baseline: 8.0914x; 1.0694x over previous
#include <cuda_runtime.h>
#include <cuda_fp16.h>
#include <math.h>
#include <stdint.h>

// Problem constants
#define Bc   2
#define Tc   512
#define Cc   768
#define Hc   12
#define HDc  64
#define Vc   50304
#define Lc   12
#define Mc   (Bc * Tc)          // 1024 rows
#define BHc  (Bc * Hc)          // 24
#define EPSc 1e-5f
#define GELU_Kc 0.7978845608028654f

// ---------------- scratch (device globals; no allocations allowed) ----------
__device__ float  g_x[Mc * Cc];
__device__ float  g_ww[Vc];
__device__ float  g_xx[Mc];

__device__ __half w_attn16[Lc * 3 * Cc * Cc];
__device__ __half w_proj16[Lc * Cc * Cc];
__device__ __half w_fc16[Lc * 4 * Cc * Cc];
__device__ __half w_fc216[Lc * Cc * 4 * Cc];
__device__ __half w_wte16[(size_t)Vc * Cc];

__device__ __half g_h16[Mc * Cc];
__device__ __half g_qkv16[Mc * 3 * Cc];
__device__ __half g_y16[Mc * Cc];
__device__ __half g_fc16[Mc * 4 * Cc];
__device__ __half g_wx16[(size_t)Mc * Vc];     // head logits staging (103MB)

// ---------------- reduction helpers -----------------------------------------
__device__ __forceinline__ float warpSum(float v) {
#pragma unroll
    for (int o = 16; o; o >>= 1) v += __shfl_xor_sync(0xffffffffu, v, o);
    return v;
}
__device__ __forceinline__ float warpMin(float v) {
#pragma unroll
    for (int o = 16; o; o >>= 1) v = fminf(v, __shfl_xor_sync(0xffffffffu, v, o));
    return v;
}
__device__ float blockSum(float v, float* sm) {
    int lane = threadIdx.x & 31, wid = threadIdx.x >> 5;
    int nw = blockDim.x >> 5;
    v = warpSum(v);
    if (lane == 0) sm[wid] = v;
    __syncthreads();
    float r = (threadIdx.x < nw) ? sm[threadIdx.x] : 0.0f;
    if (wid == 0) { r = warpSum(r); if (lane == 0) sm[0] = r; }
    __syncthreads();
    float out = sm[0];
    __syncthreads();
    return out;
}
__device__ float blockMin(float v, float* sm) {
    int lane = threadIdx.x & 31, wid = threadIdx.x >> 5;
    int nw = blockDim.x >> 5;
    v = warpMin(v);
    if (lane == 0) sm[wid] = v;
    __syncthreads();
    float r = (threadIdx.x < nw) ? sm[threadIdx.x] : INFINITY;
    if (wid == 0) { r = warpMin(r); if (lane == 0) sm[0] = r; }
    __syncthreads();
    float out = sm[0];
    __syncthreads();
    return out;
}

// ---------------- low-level asm helpers --------------------------------------
__device__ __forceinline__ void cpasync16(void* smem, const void* g, int sz) {
    unsigned a = (unsigned)__cvta_generic_to_shared(smem);
    asm volatile("cp.async.cg.shared.global [%0], [%1], 16, %2;\n"
                 :: "r"(a), "l"(g), "r"(sz));
}
#define CP_COMMIT() asm volatile("cp.async.commit_group;\n")
#define CP_WAIT0()  asm volatile("cp.async.wait_group 0;\n")
#define CP_WAIT1()  asm volatile("cp.async.wait_group 1;\n")
#define CP_WAIT2()  asm volatile("cp.async.wait_group 2;\n")

__device__ __forceinline__ void ldsm4(unsigned& r0, unsigned& r1, unsigned& r2,
                                      unsigned& r3, const __half* p) {
    unsigned a = (unsigned)__cvta_generic_to_shared(p);
    asm volatile("ldmatrix.sync.aligned.m8n8.x4.shared.b16 {%0,%1,%2,%3}, [%4];\n"
                 : "=r"(r0), "=r"(r1), "=r"(r2), "=r"(r3) : "r"(a));
}
__device__ __forceinline__ void ldsm4t(unsigned& r0, unsigned& r1, unsigned& r2,
                                       unsigned& r3, const __half* p) {
    unsigned a = (unsigned)__cvta_generic_to_shared(p);
    asm volatile("ldmatrix.sync.aligned.m8n8.x4.trans.shared.b16 {%0,%1,%2,%3}, [%4];\n"
                 : "=r"(r0), "=r"(r1), "=r"(r2), "=r"(r3) : "r"(a));
}
__device__ __forceinline__ void mma16(float* c, unsigned a0, unsigned a1,
                                      unsigned a2, unsigned a3,
                                      unsigned b0, unsigned b1) {
    asm volatile(
        "mma.sync.aligned.m16n8k16.row.col.f32.f16.f16.f32 "
        "{%0,%1,%2,%3},{%4,%5,%6,%7},{%8,%9},{%0,%1,%2,%3};\n"
        : "+f"(c[0]), "+f"(c[1]), "+f"(c[2]), "+f"(c[3])
        : "r"(a0), "r"(a1), "r"(a2), "r"(a3), "r"(b0), "r"(b1));
}

__device__ __forceinline__ float geluf(float t) {
    return 0.5f * t * (1.0f + tanhf(GELU_Kc * (t + 0.044715f * t * t * t)));
}

// ---------------- f32 -> f16 convert ------------------------------------------
__global__ void f2h_kernel(const float* __restrict__ src, __half* __restrict__ dst,
                           long n2) {
    long i = (long)blockIdx.x * blockDim.x + threadIdx.x;
    long stride = (long)gridDim.x * blockDim.x;
    const float2* s2 = (const float2*)src;
    __half2* d2 = (__half2*)dst;
    for (; i < n2; i += stride) {
        float2 v = s2[i];
        d2[i] = __floats2half2_rn(v.x, v.y);
    }
}

// ---------------- embedding ---------------------------------------------------
__global__ void embed_kernel(const int* __restrict__ idx,
                             const float* __restrict__ wte,
                             const float* __restrict__ wpe,
                             float* __restrict__ x) {
    int m = blockIdx.x;
    int t = m % Tc;
    int row = idx[m];
    const float* wr = wte + (size_t)row * Cc;
    const float* pr = wpe + (size_t)t * Cc;
    float* xr = x + (size_t)m * Cc;
    for (int c = threadIdx.x; c < Cc; c += blockDim.x)
        xr[c] = wr[c] + pr[c];
}

// ---------------- layernorm (fp16 out; optional fused sum-sq) -----------------
__global__ void ln_kernel(const float* __restrict__ in, __half* __restrict__ outh,
                          float* __restrict__ xx,
                          const float* __restrict__ w, const float* __restrict__ b) {
    __shared__ float sm[32];
    int m = blockIdx.x;
    const float* row = in + (size_t)m * Cc;
    float s = 0.f, ss = 0.f;
    for (int c = threadIdx.x; c < Cc; c += blockDim.x) {
        float v = row[c];
        s += v; ss += v * v;
    }
    float tot = blockSum(s, sm);
    float tot2 = blockSum(ss, sm);
    float mean = tot / Cc;
    float var = tot2 / Cc - mean * mean;
    float rstd = rsqrtf(var + EPSc);
    __half* oh = outh + (size_t)m * Cc;
    float s2 = 0.f;
    for (int c = threadIdx.x; c < Cc; c += blockDim.x) {
        float v = (row[c] - mean) * rstd * w[c] + b[c];
        oh[c] = __float2half_rn(v);
        s2 += v * v;
    }
    if (xx) {
        float t2 = blockSum(s2, sm);
        if (threadIdx.x == 0) xx[m] = t2;
    }
}

// ---------------- 4-stage pipelined fp16 MMA GEMM (NT): out = A @ B^T ---------
// Tile: BM = MI*32, BN = NI*32.  8 warps = 2 (m) x 4 (n).
// MODE 0: +bias | 1: +bias+residual(f32) | 2: +bias+GELU | 3: plain
// OUTH: write fp16 else fp32.
template <int MODE, bool OUTH, int MI, int NI>
__global__ __launch_bounds__(256) void gemm16(
    const __half* __restrict__ A, long ldA,
    const __half* __restrict__ B, long ldB,
    const float* __restrict__ bias, const float* __restrict__ res,
    void* __restrict__ Out, long ldO,
    int K, int Nr) {
    const int BM = MI * 32, BN = NI * 32, BK = 32, BK8 = BK + 8;
    const int NB = (NI + 1) / 2;          // n16 ldsm groups per warp
    int bm = blockIdx.y * BM;
    int bn = blockIdx.x * BN;

    extern __shared__ unsigned char dyn_raw[];
    __half* As = (__half*)dyn_raw;                         // [4][BM][BK8]
    __half* Bs = As + 4 * BM * BK8;                        // [4][BN][BK8]
#define ASM_(s, r, c) As[((s) * BM + (r)) * BK8 + (c)]
#define BSM_(s, r, c) Bs[((s) * BN + (r)) * BK8 + (c)]

    const float* Res = (MODE == 1) ? res : nullptr;
    float*  OutF = OUTH ? nullptr : (float*)Out;
    __half* OutH = OUTH ? (__half*)Out : nullptr;

    int tid = threadIdx.x;
    int lane = tid & 31;
    int wid = tid >> 5;
    int g = lane >> 2;
    int tq = lane & 3;
    int wm = (wid & 1) * (MI * 16);
    int wn = (wid >> 1) * (NI * 8);
    int lrow = lane & 15;
    int lcol = (lane >> 4) * 8;

    int lr = tid >> 2;         // 0..63
    int lk = (tid & 3) * 8;

    const __half* aP0 = A + (size_t)(bm + lr) * ldA + lk;
    const __half* aP1 = aP0 + (size_t)64 * ldA;
    int brow0 = bn + lr, brow1 = bn + lr + 64;
    int szB0 = (brow0 < Nr) ? 16 : 0;
    int szB1 = (brow1 < Nr) ? 16 : 0;
    const __half* bP0 = B + (size_t)(szB0 ? brow0 : 0) * ldB + lk;
    const __half* bP1 = B + (size_t)(szB1 ? brow1 : 0) * ldB + lk;

    float acc[MI][NI][4];
#pragma unroll
    for (int i = 0; i < MI; i++)
#pragma unroll
        for (int j = 0; j < NI; j++)
#pragma unroll
            for (int r = 0; r < 4; r++) acc[i][j][r] = 0.f;

    int nk = K / BK;

    auto load_tile = [&](int st, int kt) {
        int k0 = kt * BK;
        cpasync16(&ASM_(st, lr, lk), aP0 + k0, 16);
        if (MI == 4) cpasync16(&ASM_(st, lr + 64, lk), aP1 + k0, 16);
        cpasync16(&BSM_(st, lr, lk), bP0 + k0, szB0);
        if (NI == 4) cpasync16(&BSM_(st, lr + 64, lk), bP1 + k0, szB1);
        CP_COMMIT();
    };

    // prologue: 3 tiles in flight
    load_tile(0, 0);
    if (nk > 1) load_tile(1, 1);
    if (nk > 2) load_tile(2, 2);

    for (int kt = 0; kt < nk; kt++) {
        int pend = nk - 1 - kt;
        if (pend >= 2) { CP_WAIT2(); }
        else if (pend == 1) { CP_WAIT1(); }
        else { CP_WAIT0(); }
        __syncthreads();
        if (kt + 3 < nk) load_tile((kt + 3) & 3, kt + 3);
        int buf = kt & 3;

#pragma unroll
        for (int kp = 0; kp < 2; kp++) {
            unsigned af[MI][4];
#pragma unroll
            for (int mi = 0; mi < MI; mi++)
                ldsm4(af[mi][0], af[mi][1], af[mi][2], af[mi][3],
                      &ASM_(buf, wm + mi * 16 + lrow, kp * 16 + lcol));
            unsigned bf[NB][4];
#pragma unroll
            for (int nb = 0; nb < NB; nb++)
                ldsm4(bf[nb][0], bf[nb][1], bf[nb][2], bf[nb][3],
                      &BSM_(buf, wn + nb * 16 + lrow, kp * 16 + lcol));
#pragma unroll
            for (int mi = 0; mi < MI; mi++)
#pragma unroll
                for (int ni = 0; ni < NI; ni++) {
                    int nb = ni >> 1, wh = ni & 1;
                    mma16(acc[mi][ni],
                          af[mi][0], af[mi][1], af[mi][2], af[mi][3],
                          bf[nb][wh ? 1 : 0], bf[nb][wh ? 3 : 2]);
                }
        }
    }

    // epilogue
#pragma unroll
    for (int mi = 0; mi < MI; mi++) {
        int m = bm + wm + mi * 16 + g;
#pragma unroll
        for (int ni = 0; ni < NI; ni++) {
            int n = bn + wn + ni * 8 + tq * 2;
            if (n >= Nr) continue;
            float v0 = acc[mi][ni][0], v1 = acc[mi][ni][1];
            float v2 = acc[mi][ni][2], v3 = acc[mi][ni][3];
            if (MODE != 3) {
                float b0 = bias[n], b1 = bias[n + 1];
                v0 += b0; v1 += b1; v2 += b0; v3 += b1;
            }
            if (MODE == 1) {
                v0 += Res[(size_t)m * ldO + n];
                v1 += Res[(size_t)m * ldO + n + 1];
                v2 += Res[(size_t)(m + 8) * ldO + n];
                v3 += Res[(size_t)(m + 8) * ldO + n + 1];
            }
            if (MODE == 2) { v0 = geluf(v0); v1 = geluf(v1); v2 = geluf(v2); v3 = geluf(v3); }
            if (OUTH) {
                *(__half2*)(OutH + (size_t)m * ldO + n) = __floats2half2_rn(v0, v1);
                *(__half2*)(OutH + (size_t)(m + 8) * ldO + n) = __floats2half2_rn(v2, v3);
            } else {
                *(float2*)(OutF + (size_t)m * ldO + n) = make_float2(v0, v1);
                *(float2*)(OutF + (size_t)(m + 8) * ldO + n) = make_float2(v2, v3);
            }
        }
    }
#undef ASM_
#undef BSM_
}

// ---------------- fused flash attention ---------------------------------------
__global__ __launch_bounds__(128) void flash_kernel(const __half* __restrict__ qkv,
                                                    __half* __restrict__ y) {
    int qt = blockIdx.x, z = blockIdx.y;
    int b = z / Hc, h = z - b * Hc;
    const __half* base = qkv + (size_t)b * Tc * 3 * Cc;
    const __half* Qg = base + (size_t)qt * 64 * 3 * Cc + h * HDc;
    const __half* Kg = base + Cc + h * HDc;
    const __half* Vg = base + 2 * Cc + h * HDc;

    __shared__ __half Qs[64][72];
    __shared__ __half Ks[2][64][72];
    __shared__ __half Vs[2][64][72];

    int tid = threadIdx.x, lane = tid & 31, w = tid >> 5;
    int g = lane >> 2, tq = lane & 3;
    int lrow = lane & 15, lcol = (lane >> 4) * 8;

    for (int c = tid; c < 512; c += 128) {
        int r = c >> 3, c8 = (c & 7) * 8;
        cpasync16(&Qs[r][c8], Qg + (size_t)r * 3 * Cc + c8, 16);
        cpasync16(&Ks[0][r][c8], Kg + (size_t)r * 3 * Cc + c8, 16);
        cpasync16(&Vs[0][r][c8], Vg + (size_t)r * 3 * Cc + c8, 16);
    }
    CP_COMMIT();
    CP_WAIT0();
    __syncthreads();

    unsigned qf[4][4];
#pragma unroll
    for (int kc = 0; kc < 4; kc++)
        ldsm4(qf[kc][0], qf[kc][1], qf[kc][2], qf[kc][3],
              &Qs[w * 16 + lrow][kc * 16 + lcol]);

    float o[8][4];
#pragma unroll
    for (int i = 0; i < 8; i++)
#pragma unroll
        for (int r = 0; r < 4; r++) o[i][r] = 0.f;
    float m0 = -INFINITY, m1 = -INFINITY, l0 = 0.f, l1 = 0.f;

    int buf = 0;
    for (int j = 0; j <= qt; j++) {
        if (j + 1 <= qt) {
            for (int c = tid; c < 512; c += 128) {
                int r = c >> 3, c8 = (c & 7) * 8;
                cpasync16(&Ks[buf ^ 1][r][c8],
                          Kg + (size_t)((j + 1) * 64 + r) * 3 * Cc + c8, 16);
                cpasync16(&Vs[buf ^ 1][r][c8],
                          Vg + (size_t)((j + 1) * 64 + r) * 3 * Cc + c8, 16);
            }
            CP_COMMIT();
            CP_WAIT1();
        } else {
            CP_WAIT0();
        }
        __syncthreads();

        float s[8][4];
#pragma unroll
        for (int i = 0; i < 8; i++)
#pragma unroll
            for (int r = 0; r < 4; r++) s[i][r] = 0.f;
#pragma unroll
        for (int kc = 0; kc < 4; kc++) {
            unsigned kf[4][4];
#pragma unroll
            for (int nb = 0; nb < 4; nb++)
                ldsm4(kf[nb][0], kf[nb][1], kf[nb][2], kf[nb][3],
                      &Ks[buf][nb * 16 + lrow][kc * 16 + lcol]);
#pragma unroll
            for (int nb = 0; nb < 4; nb++) {
                mma16(s[nb * 2], qf[kc][0], qf[kc][1], qf[kc][2], qf[kc][3],
                      kf[nb][0], kf[nb][2]);
                mma16(s[nb * 2 + 1], qf[kc][0], qf[kc][1], qf[kc][2], qf[kc][3],
                      kf[nb][1], kf[nb][3]);
            }
        }
#pragma unroll
        for (int i = 0; i < 8; i++)
#pragma unroll
            for (int r = 0; r < 4; r++) s[i][r] *= 0.125f;
        if (j == qt) {
            int r0 = w * 16 + g, r1 = r0 + 8;
#pragma unroll
            for (int nt = 0; nt < 8; nt++) {
                int c0 = nt * 8 + tq * 2;
                if (c0 > r0) s[nt][0] = -1e30f;
                if (c0 + 1 > r0) s[nt][1] = -1e30f;
                if (c0 > r1) s[nt][2] = -1e30f;
                if (c0 + 1 > r1) s[nt][3] = -1e30f;
            }
        }
        float tm0 = -INFINITY, tm1 = -INFINITY;
#pragma unroll
        for (int nt = 0; nt < 8; nt++) {
            tm0 = fmaxf(tm0, fmaxf(s[nt][0], s[nt][1]));
            tm1 = fmaxf(tm1, fmaxf(s[nt][2], s[nt][3]));
        }
        tm0 = fmaxf(tm0, __shfl_xor_sync(0xffffffffu, tm0, 1));
        tm0 = fmaxf(tm0, __shfl_xor_sync(0xffffffffu, tm0, 2));
        tm1 = fmaxf(tm1, __shfl_xor_sync(0xffffffffu, tm1, 1));
        tm1 = fmaxf(tm1, __shfl_xor_sync(0xffffffffu, tm1, 2));
        float mn0 = fmaxf(m0, tm0), mn1 = fmaxf(m1, tm1);
        float a0 = __expf(m0 - mn0), a1 = __expf(m1 - mn1);
        m0 = mn0; m1 = mn1;

        float rs0 = 0.f, rs1 = 0.f;
        unsigned pa[4][4];
#pragma unroll
        for (int nt = 0; nt < 8; nt++) {
            float p0 = __expf(s[nt][0] - mn0);
            float p1 = __expf(s[nt][1] - mn0);
            float p2 = __expf(s[nt][2] - mn1);
            float p3 = __expf(s[nt][3] - mn1);
            rs0 += p0 + p1; rs1 += p2 + p3;
            int kc2 = nt >> 1, hh = (nt & 1) * 2;
            __half2 h01 = __floats2half2_rn(p0, p1);
            __half2 h23 = __floats2half2_rn(p2, p3);
            pa[kc2][hh]     = *(unsigned*)&h01;
            pa[kc2][hh + 1] = *(unsigned*)&h23;
        }
        rs0 += __shfl_xor_sync(0xffffffffu, rs0, 1);
        rs0 += __shfl_xor_sync(0xffffffffu, rs0, 2);
        rs1 += __shfl_xor_sync(0xffffffffu, rs1, 1);
        rs1 += __shfl_xor_sync(0xffffffffu, rs1, 2);
        l0 = l0 * a0 + rs0;
        l1 = l1 * a1 + rs1;
#pragma unroll
        for (int nt = 0; nt < 8; nt++) {
            o[nt][0] *= a0; o[nt][1] *= a0;
            o[nt][2] *= a1; o[nt][3] *= a1;
        }
#pragma unroll
        for (int kc2 = 0; kc2 < 4; kc2++) {
#pragma unroll
            for (int dn = 0; dn < 4; dn++) {
                unsigned v0, v1, v2, v3;
                ldsm4t(v0, v1, v2, v3,
                       &Vs[buf][kc2 * 16 + lrow][dn * 16 + lcol]);
                mma16(o[dn * 2], pa[kc2][0], pa[kc2][1], pa[kc2][2], pa[kc2][3], v0, v1);
                mma16(o[dn * 2 + 1], pa[kc2][0], pa[kc2][1], pa[kc2][2], pa[kc2][3], v2, v3);
            }
        }
        __syncthreads();
        buf ^= 1;
    }

    float il0 = 1.0f / l0, il1 = 1.0f / l1;
    int row0 = qt * 64 + w * 16 + g;
    __half* yp = y + ((size_t)(b * Tc + row0)) * Cc + h * HDc;
#pragma unroll
    for (int nt = 0; nt < 8; nt++) {
        int col = nt * 8 + tq * 2;
        *(__half2*)(yp + col) = __floats2half2_rn(o[nt][0] * il0, o[nt][1] * il0);
        *(__half2*)(yp + (size_t)8 * Cc + col) =
            __floats2half2_rn(o[nt][2] * il1, o[nt][3] * il1);
    }
}

// ---------------- head helpers ------------------------------------------------
__global__ void ww_kernel(const float* __restrict__ wte, float* __restrict__ ww) {
    __shared__ float sm[32];
    int v = blockIdx.x;
    const float* row = wte + (size_t)v * Cc;
    float s = 0.f;
    for (int c = threadIdx.x; c < Cc; c += blockDim.x) { float t = row[c]; s += t * t; }
    float tot = blockSum(s, sm);
    if (threadIdx.x == 0) ww[v] = tot;
}

// dist over fp16 wx (in-place p staging), fp32 logits out.
__global__ __launch_bounds__(512) void dist_kernel(__half* __restrict__ wx,
                                                   float* __restrict__ out,
                                                   const float* __restrict__ ww,
                                                   const float* __restrict__ xx) {
    __shared__ float sm[32];
    int m = blockIdx.x;
    __half* row = wx + (size_t)m * Vc;
    float* orow = out + (size_t)m * Vc;
    float xxm = xx[m];

    float mn = INFINITY;
    for (int v = threadIdx.x; v < Vc; v += blockDim.x) {
        float d = ww[v] + xxm - 2.0f * __half2float(row[v]);
        mn = fminf(mn, d);
    }
    float MN = blockMin(mn, sm);
    float iMN = 1.0f / MN;

    float lsum = 0.f;
    for (int v = threadIdx.x; v < Vc; v += blockDim.x) {
        float d = ww[v] + xxm - 2.0f * __half2float(row[v]);
        float r = d * iMN;
        float p = exp2f(-768.0f * __log2f(r));
        if (!isfinite(p)) p = 0.0f;
        row[v] = __float2half_rn(p);
        lsum += p;
    }
    float TOT = blockSum(lsum, sm);
    float invTot = 1.0f / TOT;
    const float floorp = 0.01f / 50304.0f;

    for (int v = threadIdx.x; v < Vc; v += blockDim.x)
        orow[v] = __logf(__half2float(row[v]) * invTot + floorp);
}

// ---------------- launch ------------------------------------------------------
extern "C" void kernel_launch(void* const* d_in, const int* in_sizes, int n_in,
                              void* d_out, int out_size) {
    const int*   idx    = (const int*)d_in[0];
    const float* wte    = (const float*)d_in[1];
    const float* wpe    = (const float*)d_in[2];
    const float* ln1_w  = (const float*)d_in[3];
    const float* ln1_b  = (const float*)d_in[4];
    const float* attn_w = (const float*)d_in[5];
    const float* attn_b = (const float*)d_in[6];
    const float* proj_w = (const float*)d_in[7];
    const float* proj_b = (const float*)d_in[8];
    const float* ln2_w  = (const float*)d_in[9];
    const float* ln2_b  = (const float*)d_in[10];
    const float* fc_w   = (const float*)d_in[11];
    const float* fc_b   = (const float*)d_in[12];
    const float* fc2_w  = (const float*)d_in[13];
    const float* fc2_b  = (const float*)d_in[14];
    const float* lnf_w  = (const float*)d_in[15];
    const float* lnf_b  = (const float*)d_in[16];
    float* out = (float*)d_out;

    float *x, *ww, *xx;
    __half *attn16, *proj16, *fcw16, *fc2w16, *wte16;
    __half *h16, *qkv16, *y16, *fcact16, *wx16;
    cudaGetSymbolAddress((void**)&x, g_x);
    cudaGetSymbolAddress((void**)&ww, g_ww);
    cudaGetSymbolAddress((void**)&xx, g_xx);
    cudaGetSymbolAddress((void**)&attn16, w_attn16);
    cudaGetSymbolAddress((void**)&proj16, w_proj16);
    cudaGetSymbolAddress((void**)&fcw16, w_fc16);
    cudaGetSymbolAddress((void**)&fc2w16, w_fc216);
    cudaGetSymbolAddress((void**)&wte16, w_wte16);
    cudaGetSymbolAddress((void**)&h16, g_h16);
    cudaGetSymbolAddress((void**)&qkv16, g_qkv16);
    cudaGetSymbolAddress((void**)&y16, g_y16);
    cudaGetSymbolAddress((void**)&fcact16, g_fc16);
    cudaGetSymbolAddress((void**)&wx16, g_wx16);

    const int S44 = 4 * (128 + 128) * 40 * 2;   // 81920 bytes
    const int S22 = 4 * (64 + 64) * 40 * 2;     // 40960 bytes
    cudaFuncSetAttribute(gemm16<0, true, 4, 4>,
                         cudaFuncAttributeMaxDynamicSharedMemorySize, S44);
    cudaFuncSetAttribute(gemm16<2, true, 4, 4>,
                         cudaFuncAttributeMaxDynamicSharedMemorySize, S44);
    cudaFuncSetAttribute(gemm16<3, true, 4, 4>,
                         cudaFuncAttributeMaxDynamicSharedMemorySize, S44);
    cudaFuncSetAttribute(gemm16<1, false, 2, 2>,
                         cudaFuncAttributeMaxDynamicSharedMemorySize, S22);

    // weight conversions
    f2h_kernel<<<4096, 256>>>(attn_w, attn16, (long)Lc * 3 * Cc * Cc / 2);
    f2h_kernel<<<4096, 256>>>(proj_w, proj16, (long)Lc * Cc * Cc / 2);
    f2h_kernel<<<4096, 256>>>(fc_w, fcw16, (long)Lc * 4 * Cc * Cc / 2);
    f2h_kernel<<<4096, 256>>>(fc2_w, fc2w16, (long)Lc * Cc * 4 * Cc / 2);
    f2h_kernel<<<4096, 256>>>(wte, wte16, (long)Vc * Cc / 2);

    embed_kernel<<<Mc, 256>>>(idx, wte, wpe, x);
    ww_kernel<<<Vc, 128>>>(wte, ww);

    for (int l = 0; l < Lc; l++) {
        const float* l1w = ln1_w + (size_t)l * Cc;
        const float* l1b = ln1_b + (size_t)l * Cc;
        const __half* aw = attn16 + (size_t)l * 3 * Cc * Cc;
        const float* ab  = attn_b + (size_t)l * 3 * Cc;
        const __half* pw = proj16 + (size_t)l * Cc * Cc;
        const float* pb  = proj_b + (size_t)l * Cc;
        const float* l2w = ln2_w + (size_t)l * Cc;
        const float* l2b = ln2_b + (size_t)l * Cc;
        const __half* fw = fcw16 + (size_t)l * 4 * Cc * Cc;
        const float* fb  = fc_b + (size_t)l * 4 * Cc;
        const __half* f2w = fc2w16 + (size_t)l * Cc * 4 * Cc;
        const float* f2b = fc2_b + (size_t)l * Cc;

        ln_kernel<<<Mc, 256>>>(x, h16, nullptr, l1w, l1b);

        // qkv16 = h @ attn_w^T + b   [1024, 2304]
        gemm16<0, true, 4, 4><<<dim3(18, 8), 256, S44>>>(
            h16, Cc, aw, Cc, ab, nullptr, qkv16, 3 * Cc, Cc, 3 * Cc);

        // fused attention -> y16
        flash_kernel<<<dim3(8, BHc), 128>>>(qkv16, y16);

        // x = x + y @ proj_w^T + proj_b   (fp32 out), 64x64 tiles: grid 192
        gemm16<1, false, 2, 2><<<dim3(12, 16), 256, S22>>>(
            y16, Cc, pw, Cc, pb, x, x, Cc, Cc, Cc);

        ln_kernel<<<Mc, 256>>>(x, h16, nullptr, l2w, l2b);

        // fc16 = gelu(h @ fc_w^T + fc_b)  [1024, 3072]
        gemm16<2, true, 4, 4><<<dim3(24, 8), 256, S44>>>(
            h16, Cc, fw, Cc, fb, nullptr, fcact16, 4 * Cc, Cc, 4 * Cc);

        // x = x + fc @ fc2_w^T + fc2_b   64x64 tiles: grid 192
        gemm16<1, false, 2, 2><<<dim3(12, 16), 256, S22>>>(
            fcact16, 4 * Cc, f2w, 4 * Cc, f2b, x, x, Cc, 4 * Cc, Cc);
    }

    // final LN (+ fused xx) + head
    ln_kernel<<<Mc, 256>>>(x, h16, xx, lnf_w, lnf_b);

    // wx16 = h @ wte^T  [1024, 50304] (fp16 out)
    gemm16<3, true, 4, 4><<<dim3(Vc / 128, 8), 256, S44>>>(
        h16, Cc, wte16, Cc, nullptr, nullptr, wx16, Vc, Cc, Vc);

    dist_kernel<<<Mc, 512>>>(wx16, out, ww, xx);
}